// round 4
// baseline (speedup 1.0000x reference)
#include <cuda_runtime.h>
#include <math.h>

#define NN 8192
#define LL 512
#define KK 30

typedef unsigned long long ull;

// ---------------- packed f32x2 helpers (sm_103a FFMA2) ----------------
__device__ __forceinline__ ull pk2(float a, float b) {
    ull r; asm("mov.b64 %0, {%1,%2};" : "=l"(r) : "f"(a), "f"(b)); return r;
}
__device__ __forceinline__ void upk2(ull v, float& a, float& b) {
    asm("mov.b64 {%0,%1}, %2;" : "=f"(a), "=f"(b) : "l"(v));
}
__device__ __forceinline__ ull fma2(ull x, ull y, ull a) {
    ull r; asm("fma.rn.f32x2 %0, %1, %2, %3;" : "=l"(r) : "l"(x), "l"(y), "l"(a));
    return r;
}

// ---------------- device scratch ----------------
__device__ int   g_knn [NN * KK];
__device__ float g_dist[NN * KK];
__device__ float g_Psrc[NN * 128];
__device__ float g_Ptgt[NN * 128];
__device__ float g_Vnode[NN * 256];
__device__ float g_posA[1023 * 128];
__device__ float g_woT[32 * 64];    // Wo transposed [o][cc]
__device__ float g_w2T[32 * 32];    // W2 transposed [o][j]

// ================= prep kernel: knn | posA | node | transpose =================
__global__ void k_prep(const float* __restrict__ trans,
                       const float* __restrict__ rots,
                       const float* __restrict__ node_emb,
                       const unsigned char* __restrict__ xm,
                       const unsigned char* __restrict__ nm,
                       const float* __restrict__ Wa,
                       const float* __restrict__ Wv,
                       const float* __restrict__ Wo,
                       const float* __restrict__ W2)
{
    __shared__ float sx[LL], sy[LL], sz[LL];
    __shared__ float semb[8][4][36];
    __shared__ float trig[16];
    __shared__ int   s_u8;
    int bid = blockIdx.x, t = threadIdx.x;

    if (bid < 2048) {
        // ---------- kNN: 4 targets / block, warp per target ----------
        int g0 = bid * 4;
        int base = (g0 >> 9) << 9;
        for (int i = t; i < LL; i += 128) {
            const float* p = trans + (size_t)(base + i) * 3;
            sx[i] = p[0]; sy[i] = p[1]; sz[i] = p[2];
        }
        __syncthreads();
        int warp = t >> 5, lane = t & 31;
        int tgt = g0 + warp;
        int tl = tgt & 511;
        float px = sx[tl], py = sy[tl], pz = sz[tl];
        float d[16];
#pragma unroll
        for (int q = 0; q < 16; q++) {
            int c = lane + (q << 5);
            float dx = sx[c] - px, dy = sy[c] - py, dz = sz[c] - pz;
            float d2 = dx * dx + dy * dy + dz * dz;
            d[q] = (c == tl) ? 1e30f : d2;
        }
        for (int it = 0; it < KK; it++) {
            float bv = d[0]; int bq = 0;
#pragma unroll
            for (int q = 1; q < 16; q++)
                if (d[q] < bv) { bv = d[q]; bq = q; }
            int bi = lane + (bq << 5);
#pragma unroll
            for (int off = 16; off > 0; off >>= 1) {
                float ov = __shfl_down_sync(0xffffffffu, bv, off);
                int   oi = __shfl_down_sync(0xffffffffu, bi, off);
                if (ov < bv || (ov == bv && oi < bi)) { bv = ov; bi = oi; }
            }
            bv = __shfl_sync(0xffffffffu, bv, 0);
            bi = __shfl_sync(0xffffffffu, bi, 0);
            if (lane == (bi & 31)) {
                int wq = bi >> 5;
#pragma unroll
                for (int q = 0; q < 16; q++)
                    if (q == wq) d[q] = 1e30f;
            }
            if (lane == 0) {
                g_knn [tgt * KK + it] = base + bi;
                g_dist[tgt * KK + it] = sqrtf(bv);
            }
        }
    } else if (bid < 2048 + 1023) {
        // ---------- posA table ----------
        int dd = bid - 2048;
        float delta = (float)(dd - 511);
        if (t < 8) {
            float freq = expf(-(float)(2 * t) * (9.210340371976184f / 16.0f));
            float ang = delta * freq;
            trig[t]     = cosf(ang);
            trig[8 + t] = sinf(ang);
        }
        __syncthreads();
        float s = 0.f;
#pragma unroll
        for (int j = 0; j < 8; j++) {
            s = fmaf(trig[j],     Wa[(86 + j) * 128 + t], s);
            s = fmaf(trig[8 + j], Wa[(94 + j) * 128 + t], s);
        }
        g_posA[dd * 128 + t] = s;
    } else if (bid < 2048 + 1023 + 1024) {
        // ---------- node precompute: 8 nodes / block ----------
        int n0 = (bid - (2048 + 1023)) * 8;
        if (t < 64) {
            int any = 0;
#pragma unroll
            for (int j = 1; j < 4; j++) any |= (int)xm[4 * t + j];
            unsigned b = __ballot_sync(0xffffffffu, any != 0);
            if (t == 0) s_u8 = (b != 0u) ? 1 : 0;
        }
        __syncthreads();
        int u8 = s_u8;
        for (int m = 0; m < 8; m++) {
            int n = n0 + m;
            int r = t >> 5, c = t & 31;
            semb[m][r][c] = node_emb[n * 128 + t];
            if (t == 0) {
                const float* R = rots + n * 9;
                const float bx0 = -0.525f, by0 = 1.363f, bx2 = 1.526f;
#pragma unroll
                for (int i = 0; i < 3; i++) {
                    float r0 = R[i * 3 + 0], r1 = R[i * 3 + 1];
                    semb[m][1 + i][32 + 0] = r0 * bx0 + r1 * by0;
                    semb[m][1 + i][32 + 1] = 0.f;
                    semb[m][1 + i][32 + 2] = r0 * bx2;
                }
                int xv = u8 ? (int)xm[n] : (int)xm[n * 4];
                int nv = u8 ? (int)nm[n] : (int)nm[n * 4];
                semb[m][0][32] = 0.f;
                semb[m][0][33] = 0.f;
                semb[m][0][34] = (nv && !xv) ? 1.f : 0.f;
            }
        }
        __syncthreads();
        ull acc2[8];
#pragma unroll
        for (int m = 0; m < 8; m++) acc2[m] = 0ull;
        for (int ch = 0; ch < 35; ch++) {
            ull w2 = pk2(Wa[ch * 128 + t], Wa[(35 + ch) * 128 + t]);
#pragma unroll
            for (int m = 0; m < 8; m++) {
                float e0 = semb[m][0][ch];
                acc2[m] = fma2(pk2(e0, e0), w2, acc2[m]);
            }
        }
#pragma unroll
        for (int m = 0; m < 8; m++) {
            float s, tt; upk2(acc2[m], s, tt);
            g_Psrc[(n0 + m) * 128 + t] = s;
            g_Ptgt[(n0 + m) * 128 + t] = tt;
        }
        int c = t & 63, r0 = t >> 6;
        ull v2[8];
#pragma unroll
        for (int m = 0; m < 8; m++) v2[m] = 0ull;
        for (int ch = 0; ch < 35; ch++) {
            float w = Wv[ch * 64 + c];
            ull wd = pk2(w, w);
#pragma unroll
            for (int m = 0; m < 8; m++)
                v2[m] = fma2(pk2(semb[m][r0][ch], semb[m][r0 + 2][ch]), wd, v2[m]);
        }
#pragma unroll
        for (int m = 0; m < 8; m++) {
            float a, b; upk2(v2[m], a, b);
            g_Vnode[(n0 + m) * 256 + t]       = a;
            g_Vnode[(n0 + m) * 256 + 128 + t] = b;
        }
    } else {
        for (int idx = t; idx < 2048; idx += 128) {
            int o = idx & 31, cc = idx >> 5;
            g_woT[o * 64 + cc] = Wo[idx];
        }
        for (int idx = t; idx < 1024; idx += 128) {
            int o = idx & 31, j = idx >> 5;
            g_w2T[o * 32 + j] = W2[idx];
        }
    }
}

// ================= main kernel: one block per target node =================
__global__ void __launch_bounds__(128)
k_main(const float* __restrict__ Wa,
       const float* __restrict__ avec,
       const float* __restrict__ Wg,
       float* __restrict__ out)
{
    __shared__ __align__(16) float s_rbf[KK][16];
    __shared__ __align__(16) float s_agg[256];
    __shared__ float s_logit[KK][8];
    __shared__ float s_alpha[KK][8];
    __shared__ float s_y[128];
    __shared__ float s_yg[128];
    __shared__ float s_gate[32];
    __shared__ int   s_src[KK];
    __shared__ float s_dist[KK];
    __shared__ float s_valid[KK];

    int n = blockIdx.x, t = threadIdx.x;

    if (t < KK) {
        int s = g_knn[n * KK + t];
        float d = g_dist[n * KK + t];
        s_src[t] = s;
        s_dist[t] = d;
        s_valid[t] = (isfinite(d) && d > 1e-3f) ? 1.f : 0.f;
    }
    // RBF weight rows 70..85 of W_alpha, prepacked in j-pairs (column t)
    ull arbp[8];
#pragma unroll
    for (int jj = 0; jj < 8; jj++)
        arbp[jj] = pk2(Wa[(70 + 2 * jj) * 128 + t], Wa[(71 + 2 * jj) * 128 + t]);
    float av = avec[t];                   // t = h*16+k
    float ptgt = g_Ptgt[n * 128 + t];
    __syncthreads();

    // ---- RBF features ----
    for (int i = t; i < KK * 16; i += 128) {
        int e = i >> 4, j = i & 15;
        float x = (s_dist[e] - (float)j * (20.0f / 15.0f)) * 0.8f;
        s_rbf[e][j] = __expf(-x * x);
    }
    __syncthreads();

    // ---- logits: fused, 2 edges per iteration, LDS.128 rbf + FMA2 ----
    for (int e = 0; e < KK; e += 2) {
        int s0 = s_src[e], s1 = s_src[e + 1];
        float b0 = ptgt + g_Psrc[(size_t)s0 * 128 + t]
                        + g_posA[(size_t)(s0 - n + 511) * 128 + t];
        float b1 = ptgt + g_Psrc[(size_t)s1 * 128 + t]
                        + g_posA[(size_t)(s1 - n + 511) * 128 + t];
        ull acc0 = pk2(b0, 0.f);
        ull acc1 = pk2(b1, 0.f);
        const ulonglong2* r0p = reinterpret_cast<const ulonglong2*>(&s_rbf[e][0]);
        const ulonglong2* r1p = reinterpret_cast<const ulonglong2*>(&s_rbf[e + 1][0]);
#pragma unroll
        for (int jj = 0; jj < 4; jj++) {
            ulonglong2 ra = r0p[jj];
            ulonglong2 rb = r1p[jj];
            acc0 = fma2(ra.x, arbp[2 * jj],     acc0);
            acc1 = fma2(rb.x, arbp[2 * jj],     acc1);
            acc0 = fma2(ra.y, arbp[2 * jj + 1], acc0);
            acc1 = fma2(rb.y, arbp[2 * jj + 1], acc1);
        }
        float u0, u1, u2, u3;
        upk2(acc0, u0, u1);  float x0 = u0 + u1;
        upk2(acc1, u2, u3);  float x1 = u2 + u3;
        float h0 = x0 / (1.f + __expf(-x0));
        float h1 = x1 / (1.f + __expf(-x1));
        float q0 = h0 * av;
        float q1 = h1 * av;
        q0 += __shfl_xor_sync(0xffffffffu, q0, 8);
        q1 += __shfl_xor_sync(0xffffffffu, q1, 8);
        q0 += __shfl_xor_sync(0xffffffffu, q0, 4);
        q1 += __shfl_xor_sync(0xffffffffu, q1, 4);
        q0 += __shfl_xor_sync(0xffffffffu, q0, 2);
        q1 += __shfl_xor_sync(0xffffffffu, q1, 2);
        q0 += __shfl_xor_sync(0xffffffffu, q0, 1);
        q1 += __shfl_xor_sync(0xffffffffu, q1, 1);
        if ((t & 15) == 0) {
            float l0 = (q0 > 0.f) ? q0 : 0.2f * q0;
            float l1 = (q1 > 0.f) ? q1 : 0.2f * q1;
            s_logit[e]    [t >> 4] = (s_valid[e]     > 0.f) ? l0 : -1e9f;
            s_logit[e + 1][t >> 4] = (s_valid[e + 1] > 0.f) ? l1 : -1e9f;
        }
    }
    __syncthreads();

    // ---- per-head softmax over 30 edges (warp 0, 4 lanes per head) ----
    if (t < 32) {
        int h = t >> 2, q = t & 3;
        float mx = -1e30f;
        for (int e = q; e < KK; e += 4) mx = fmaxf(mx, s_logit[e][h]);
        mx = fmaxf(mx, __shfl_xor_sync(0xffffffffu, mx, 1));
        mx = fmaxf(mx, __shfl_xor_sync(0xffffffffu, mx, 2));
        float den = 0.f;
        for (int e = q; e < KK; e += 4) {
            float ex = __expf(s_logit[e][h] - mx) * s_valid[e];
            s_alpha[e][h] = ex; den += ex;
        }
        den += __shfl_xor_sync(0xffffffffu, den, 1);
        den += __shfl_xor_sync(0xffffffffu, den, 2);
        float inv = 1.f / (den + 1e-9f);
        for (int e = q; e < KK; e += 4) s_alpha[e][h] *= inv;
    }
    __syncthreads();

    // ---- value aggregation: thread owns channel pair 2t, LDG.64 + FMA2 ----
    {
        int off = 2 * t;                 // [0,256)
        int h = (off & 63) >> 3;         // head (same for both channels)
        ull acc = 0ull;
#pragma unroll 2
        for (int e = 0; e < KK; e += 2) {
            int src0 = s_src[e], src1 = s_src[e + 1];
            float al0 = s_alpha[e][h];
            float al1 = s_alpha[e + 1][h];
            ull v0 = *reinterpret_cast<const ull*>(g_Vnode + (size_t)src0 * 256 + off);
            ull v1 = *reinterpret_cast<const ull*>(g_Vnode + (size_t)src1 * 256 + off);
            acc = fma2(v0, pk2(al0, al0), acc);
            acc = fma2(v1, pk2(al1, al1), acc);
        }
        *reinterpret_cast<ull*>(&s_agg[off]) = acc;
    }
    __syncthreads();

    // ---- epilogue: y = agg @ Wo ; gate ; out ----
    int r = t >> 5, o = t & 31;
    {
        ull acc = 0ull;
        const ull* ap = reinterpret_cast<const ull*>(&s_agg[r * 64]);
        const ull* wp = reinterpret_cast<const ull*>(&g_woT[o * 64]);
#pragma unroll
        for (int k = 0; k < 32; k++) acc = fma2(ap[k], wp[k], acc);
        float a, b; upk2(acc, a, b);
        s_y[t] = a + b;
    }
    __syncthreads();
    if (t < 32) {
        float g = 0.f;
#pragma unroll
        for (int j = 0; j < 32; j++) g = fmaf(s_y[j], Wg[j * 32 + t], g);
        s_gate[t] = g / (1.f + __expf(-g));
    }
    __syncthreads();
    s_yg[t] = s_y[t] * s_gate[o];
    __syncthreads();
    {
        ull acc = 0ull;
        const ull* yp = reinterpret_cast<const ull*>(&s_yg[r * 32]);
        const ull* wp = reinterpret_cast<const ull*>(&g_w2T[o * 32]);
#pragma unroll
        for (int k = 0; k < 16; k++) acc = fma2(yp[k], wp[k], acc);
        float a, b; upk2(acc, a, b);
        out[n * 128 + t] = a + b;
    }
}

// ---------------- launch ----------------
extern "C" void kernel_launch(void* const* d_in, const int* in_sizes, int n_in,
                              void* d_out, int out_size)
{
    const float* rots     = (const float*)d_in[0];
    const float* trans    = (const float*)d_in[1];
    const float* node_emb = (const float*)d_in[2];
    const unsigned char* xm = (const unsigned char*)d_in[4];
    const unsigned char* nm = (const unsigned char*)d_in[5];
    const float* Wa = (const float*)d_in[6];
    const float* av = (const float*)d_in[7];
    const float* Wv = (const float*)d_in[8];
    const float* Wo = (const float*)d_in[9];
    const float* Wg = (const float*)d_in[10];
    const float* W2 = (const float*)d_in[11];
    float* out = (float*)d_out;

    k_prep<<<4096, 128>>>(trans, rots, node_emb, xm, nm, Wa, Wv, Wo, W2);
    k_main<<<NN, 128>>>(Wa, av, Wg, out);
}

// round 5
// speedup vs baseline: 1.8069x; 1.8069x over previous
#include <cuda_runtime.h>
#include <math.h>

#define NN 8192
#define LL 512
#define KK 30

typedef unsigned long long ull;

// ---------------- packed f32x2 helpers (used in k_prep only) ----------------
__device__ __forceinline__ ull pk2(float a, float b) {
    ull r; asm("mov.b64 %0, {%1,%2};" : "=l"(r) : "f"(a), "f"(b)); return r;
}
__device__ __forceinline__ void upk2(ull v, float& a, float& b) {
    asm("mov.b64 {%0,%1}, %2;" : "=f"(a), "=f"(b) : "l"(v));
}
__device__ __forceinline__ ull fma2(ull x, ull y, ull a) {
    ull r; asm("fma.rn.f32x2 %0, %1, %2, %3;" : "=l"(r) : "l"(x), "l"(y), "l"(a));
    return r;
}

// ---------------- device scratch ----------------
__device__ int   g_knn [NN * KK];
__device__ float g_dist[NN * KK];
__device__ float g_Psrc[NN * 128];
__device__ float g_Ptgt[NN * 128];
__device__ float g_Vnode[NN * 256];
__device__ float g_posA[1023 * 128];

// ================= prep kernel: knn | posA | node =================
__global__ void k_prep(const float* __restrict__ trans,
                       const float* __restrict__ rots,
                       const float* __restrict__ node_emb,
                       const unsigned char* __restrict__ xm,
                       const unsigned char* __restrict__ nm,
                       const float* __restrict__ Wa,
                       const float* __restrict__ Wv)
{
    __shared__ float sx[LL], sy[LL], sz[LL];
    __shared__ float semb[8][4][36];
    __shared__ float trig[16];
    __shared__ int   s_u8;
    int bid = blockIdx.x, t = threadIdx.x;

    if (bid < 2048) {
        // ---------- kNN: 4 targets / block, warp per target ----------
        int g0 = bid * 4;
        int base = (g0 >> 9) << 9;
        for (int i = t; i < LL; i += 128) {
            const float* p = trans + (size_t)(base + i) * 3;
            sx[i] = p[0]; sy[i] = p[1]; sz[i] = p[2];
        }
        __syncthreads();
        int warp = t >> 5, lane = t & 31;
        int tgt = g0 + warp;
        int tl = tgt & 511;
        float px = sx[tl], py = sy[tl], pz = sz[tl];
        float d[16];
#pragma unroll
        for (int q = 0; q < 16; q++) {
            int c = lane + (q << 5);
            float dx = sx[c] - px, dy = sy[c] - py, dz = sz[c] - pz;
            float d2 = dx * dx + dy * dy + dz * dz;
            d[q] = (c == tl) ? 1e30f : d2;
        }
        for (int it = 0; it < KK; it++) {
            float bv = d[0]; int bq = 0;
#pragma unroll
            for (int q = 1; q < 16; q++)
                if (d[q] < bv) { bv = d[q]; bq = q; }
            int bi = lane + (bq << 5);
#pragma unroll
            for (int off = 16; off > 0; off >>= 1) {
                float ov = __shfl_down_sync(0xffffffffu, bv, off);
                int   oi = __shfl_down_sync(0xffffffffu, bi, off);
                if (ov < bv || (ov == bv && oi < bi)) { bv = ov; bi = oi; }
            }
            bv = __shfl_sync(0xffffffffu, bv, 0);
            bi = __shfl_sync(0xffffffffu, bi, 0);
            if (lane == (bi & 31)) {
                int wq = bi >> 5;
#pragma unroll
                for (int q = 0; q < 16; q++)
                    if (q == wq) d[q] = 1e30f;
            }
            if (lane == 0) {
                g_knn [tgt * KK + it] = base + bi;
                g_dist[tgt * KK + it] = sqrtf(bv);
            }
        }
    } else if (bid < 2048 + 1023) {
        // ---------- posA table ----------
        int dd = bid - 2048;
        float delta = (float)(dd - 511);
        if (t < 8) {
            float freq = expf(-(float)(2 * t) * (9.210340371976184f / 16.0f));
            float ang = delta * freq;
            trig[t]     = cosf(ang);
            trig[8 + t] = sinf(ang);
        }
        __syncthreads();
        float s = 0.f;
#pragma unroll
        for (int j = 0; j < 8; j++) {
            s = fmaf(trig[j],     Wa[(86 + j) * 128 + t], s);
            s = fmaf(trig[8 + j], Wa[(94 + j) * 128 + t], s);
        }
        g_posA[dd * 128 + t] = s;
    } else {
        // ---------- node precompute: 8 nodes / block ----------
        int n0 = (bid - (2048 + 1023)) * 8;
        if (t < 64) {
            int any = 0;
#pragma unroll
            for (int j = 1; j < 4; j++) any |= (int)xm[4 * t + j];
            unsigned b = __ballot_sync(0xffffffffu, any != 0);
            if (t == 0) s_u8 = (b != 0u) ? 1 : 0;
        }
        __syncthreads();
        int u8 = s_u8;
        for (int m = 0; m < 8; m++) {
            int n = n0 + m;
            int r = t >> 5, c = t & 31;
            semb[m][r][c] = node_emb[n * 128 + t];
            if (t == 0) {
                const float* R = rots + n * 9;
                const float bx0 = -0.525f, by0 = 1.363f, bx2 = 1.526f;
#pragma unroll
                for (int i = 0; i < 3; i++) {
                    float r0 = R[i * 3 + 0], r1 = R[i * 3 + 1];
                    semb[m][1 + i][32 + 0] = r0 * bx0 + r1 * by0;
                    semb[m][1 + i][32 + 1] = 0.f;
                    semb[m][1 + i][32 + 2] = r0 * bx2;
                }
                int xv = u8 ? (int)xm[n] : (int)xm[n * 4];
                int nv = u8 ? (int)nm[n] : (int)nm[n * 4];
                semb[m][0][32] = 0.f;
                semb[m][0][33] = 0.f;
                semb[m][0][34] = (nv && !xv) ? 1.f : 0.f;
            }
        }
        __syncthreads();
        ull acc2[8];
#pragma unroll
        for (int m = 0; m < 8; m++) acc2[m] = 0ull;
        for (int ch = 0; ch < 35; ch++) {
            ull w2 = pk2(Wa[ch * 128 + t], Wa[(35 + ch) * 128 + t]);
#pragma unroll
            for (int m = 0; m < 8; m++) {
                float e0 = semb[m][0][ch];
                acc2[m] = fma2(pk2(e0, e0), w2, acc2[m]);
            }
        }
#pragma unroll
        for (int m = 0; m < 8; m++) {
            float s, tt; upk2(acc2[m], s, tt);
            g_Psrc[(n0 + m) * 128 + t] = s;
            g_Ptgt[(n0 + m) * 128 + t] = tt;
        }
        int c = t & 63, r0 = t >> 6;
        ull v2[8];
#pragma unroll
        for (int m = 0; m < 8; m++) v2[m] = 0ull;
        for (int ch = 0; ch < 35; ch++) {
            float w = Wv[ch * 64 + c];
            ull wd = pk2(w, w);
#pragma unroll
            for (int m = 0; m < 8; m++)
                v2[m] = fma2(pk2(semb[m][r0][ch], semb[m][r0 + 2][ch]), wd, v2[m]);
        }
#pragma unroll
        for (int m = 0; m < 8; m++) {
            float a, b; upk2(v2[m], a, b);
            g_Vnode[(n0 + m) * 256 + t]       = a;
            g_Vnode[(n0 + m) * 256 + 128 + t] = b;
        }
    }
}

// ================= main kernel: one block per target node (R1 topology) =====
__global__ void __launch_bounds__(128)
k_main(const float* __restrict__ Wa,
       const float* __restrict__ avec,
       const float* __restrict__ Wo,
       const float* __restrict__ Wg,
       const float* __restrict__ W2,
       float* __restrict__ out)
{
    __shared__ __align__(16) float s_rbf[KK][16];
    __shared__ __align__(16) float s_agg[256];
    __shared__ float s_logit[KK][8];
    __shared__ float s_alpha[KK][8];
    __shared__ float s_y[128];
    __shared__ float s_gate[32];
    __shared__ int   s_src[KK];
    __shared__ float s_dist[KK];
    __shared__ float s_valid[KK];

    int n = blockIdx.x, t = threadIdx.x;
    if (t < KK) {
        int s = g_knn[n * KK + t];
        float d = g_dist[n * KK + t];
        s_src[t] = s;
        s_dist[t] = d;
        s_valid[t] = (isfinite(d) && d > 1e-3f) ? 1.f : 0.f;
    }
    float ptgt = g_Ptgt[n * 128 + t];
    float av = avec[t];                 // a_vec flat: t = h*16+k
    float arb[16];
#pragma unroll
    for (int j = 0; j < 16; j++) arb[j] = Wa[(70 + j) * 128 + t];  // RBF rows
    __syncthreads();
    // RBF features: mu = linspace(0,20,16), sigma = 1.25
    for (int i = t; i < KK * 16; i += 128) {
        int e = i >> 4, j = i & 15;
        float x = (s_dist[e] - (float)j * (20.0f / 15.0f)) * 0.8f;
        s_rbf[e][j] = __expf(-x * x);
    }
    __syncthreads();
    // ---- logits (R1 structure; rbf read as float4 broadcast LDS.128) ----
    for (int e = 0; e < KK; e++) {
        int src = s_src[e];
        float acc = ptgt + g_Psrc[(size_t)src * 128 + t]
                         + g_posA[(size_t)(src - n + 511) * 128 + t];
        const float4* rp = reinterpret_cast<const float4*>(&s_rbf[e][0]);
#pragma unroll
        for (int jj = 0; jj < 4; jj++) {
            float4 r4 = rp[jj];
            acc = fmaf(r4.x, arb[4 * jj + 0], acc);
            acc = fmaf(r4.y, arb[4 * jj + 1], acc);
            acc = fmaf(r4.z, arb[4 * jj + 2], acc);
            acc = fmaf(r4.w, arb[4 * jj + 3], acc);
        }
        float hd = acc / (1.f + __expf(-acc));       // silu
        float p = hd * av;
        p += __shfl_xor_sync(0xffffffffu, p, 8);
        p += __shfl_xor_sync(0xffffffffu, p, 4);
        p += __shfl_xor_sync(0xffffffffu, p, 2);
        p += __shfl_xor_sync(0xffffffffu, p, 1);
        if ((t & 15) == 0) {
            float lg = (p > 0.f) ? p : 0.2f * p;     // leaky_relu 0.2
            s_logit[e][t >> 4] = (s_valid[e] > 0.f) ? lg : -1e9f;
        }
    }
    __syncthreads();
    // ---- per-head softmax over the 30 incoming edges ----
    if (t < 8) {
        float mx = -1e30f;
        for (int e = 0; e < KK; e++) mx = fmaxf(mx, s_logit[e][t]);
        float den = 0.f;
        for (int e = 0; e < KK; e++) {
            float ex = __expf(s_logit[e][t] - mx) * s_valid[e];
            s_alpha[e][t] = ex; den += ex;
        }
        float inv = 1.f / (den + 1e-9f);
        for (int e = 0; e < KK; e++) s_alpha[e][t] *= inv;
    }
    __syncthreads();
    // ---- value aggregation: thread owns channel pair 2t (LDG.64, plain fmaf)
    {
        int off = 2 * t;                  // [0,256)
        int h = (off & 63) >> 3;          // head (same for both channels of pair)
        float a0 = 0.f, a1 = 0.f;
#pragma unroll
        for (int e = 0; e < KK; e++) {
            float al = s_alpha[e][h];
            float2 v = *reinterpret_cast<const float2*>(
                g_Vnode + (size_t)s_src[e] * 256 + off);
            a0 = fmaf(al, v.x, a0);
            a1 = fmaf(al, v.y, a1);
        }
        s_agg[off] = a0; s_agg[off + 1] = a1;
    }
    __syncthreads();
    // ---- epilogue (R1 coalesced layout): y = agg @ Wo ; gate ; out ----
    int r = t >> 5, o = t & 31;
    float y = 0.f;
#pragma unroll
    for (int cc = 0; cc < 64; cc++)
        y = fmaf(s_agg[r * 64 + cc], Wo[cc * 32 + o], y);
    s_y[t] = y;
    __syncthreads();
    if (t < 32) {
        float g = 0.f;
#pragma unroll
        for (int j = 0; j < 32; j++) g = fmaf(s_y[j], Wg[j * 32 + t], g);
        s_gate[t] = g / (1.f + __expf(-g));          // silu gate
    }
    __syncthreads();
    float oo = 0.f;
#pragma unroll
    for (int j = 0; j < 32; j++)
        oo = fmaf(s_y[r * 32 + j] * s_gate[j], W2[j * 32 + o], oo);
    out[n * 128 + t] = oo;
}

// ---------------- launch ----------------
extern "C" void kernel_launch(void* const* d_in, const int* in_sizes, int n_in,
                              void* d_out, int out_size)
{
    const float* rots     = (const float*)d_in[0];
    const float* trans    = (const float*)d_in[1];
    const float* node_emb = (const float*)d_in[2];
    const unsigned char* xm = (const unsigned char*)d_in[4];
    const unsigned char* nm = (const unsigned char*)d_in[5];
    const float* Wa = (const float*)d_in[6];
    const float* av = (const float*)d_in[7];
    const float* Wv = (const float*)d_in[8];
    const float* Wo = (const float*)d_in[9];
    const float* Wg = (const float*)d_in[10];
    const float* W2 = (const float*)d_in[11];
    float* out = (float*)d_out;

    k_prep<<<2048 + 1023 + 1024, 128>>>(trans, rots, node_emb, xm, nm, Wa, Wv);
    k_main<<<NN, 128>>>(Wa, av, Wo, Wg, W2, out);
}

// round 6
// speedup vs baseline: 2.1218x; 1.1743x over previous
#include <cuda_runtime.h>
#include <math.h>

#define NN 8192
#define LL 512
#define KK 30
#define TB 2048                 // rbf table bins over [0,24)
#define TB_SCALE (2048.0f / 24.0f)

typedef unsigned long long ull;

// ---------------- packed f32x2 helpers (used in k_prep only) ----------------
__device__ __forceinline__ ull pk2(float a, float b) {
    ull r; asm("mov.b64 %0, {%1,%2};" : "=l"(r) : "f"(a), "f"(b)); return r;
}
__device__ __forceinline__ void upk2(ull v, float& a, float& b) {
    asm("mov.b64 {%0,%1}, %2;" : "=f"(a), "=f"(b) : "l"(v));
}
__device__ __forceinline__ ull fma2(ull x, ull y, ull a) {
    ull r; asm("fma.rn.f32x2 %0, %1, %2, %3;" : "=l"(r) : "l"(x), "l"(y), "l"(a));
    return r;
}

// ---------------- device scratch ----------------
__device__ int   g_knn [NN * KK];
__device__ float g_dist[NN * KK];
__device__ float g_Psrc[NN * 128];
__device__ float g_Ptgt[NN * 128];
__device__ float g_Vnode[NN * 256];
__device__ float g_posA[1023 * 128];
__device__ float g_rbfT[TB * 128];   // rbf(d) . Wa[70:86]  lerp table

// ================= prep kernel: knn | posA | node | rbf-table ==============
__global__ void k_prep(const float* __restrict__ trans,
                       const float* __restrict__ rots,
                       const float* __restrict__ node_emb,
                       const unsigned char* __restrict__ xm,
                       const unsigned char* __restrict__ nm,
                       const float* __restrict__ Wa,
                       const float* __restrict__ Wv)
{
    __shared__ float sx[LL], sy[LL], sz[LL];
    __shared__ float semb[8][4][36];
    __shared__ float trig[16];
    __shared__ int   s_u8;
    int bid = blockIdx.x, t = threadIdx.x;

    if (bid < 2048) {
        // ---------- kNN: 4 targets / block, warp per target ----------
        int g0 = bid * 4;
        int base = (g0 >> 9) << 9;
        for (int i = t; i < LL; i += 128) {
            const float* p = trans + (size_t)(base + i) * 3;
            sx[i] = p[0]; sy[i] = p[1]; sz[i] = p[2];
        }
        __syncthreads();
        int warp = t >> 5, lane = t & 31;
        int tgt = g0 + warp;
        int tl = tgt & 511;
        float px = sx[tl], py = sy[tl], pz = sz[tl];
        float d[16];
#pragma unroll
        for (int q = 0; q < 16; q++) {
            int c = lane + (q << 5);
            float dx = sx[c] - px, dy = sy[c] - py, dz = sz[c] - pz;
            float d2 = dx * dx + dy * dy + dz * dz;
            d[q] = (c == tl) ? 1e30f : d2;
        }
        for (int it = 0; it < KK; it++) {
            float bv = d[0]; int bq = 0;
#pragma unroll
            for (int q = 1; q < 16; q++)
                if (d[q] < bv) { bv = d[q]; bq = q; }
            int bi = lane + (bq << 5);
#pragma unroll
            for (int off = 16; off > 0; off >>= 1) {
                float ov = __shfl_down_sync(0xffffffffu, bv, off);
                int   oi = __shfl_down_sync(0xffffffffu, bi, off);
                if (ov < bv || (ov == bv && oi < bi)) { bv = ov; bi = oi; }
            }
            bv = __shfl_sync(0xffffffffu, bv, 0);
            bi = __shfl_sync(0xffffffffu, bi, 0);
            if (lane == (bi & 31)) {
                int wq = bi >> 5;
#pragma unroll
                for (int q = 0; q < 16; q++)
                    if (q == wq) d[q] = 1e30f;
            }
            if (lane == 0) {
                g_knn [tgt * KK + it] = base + bi;
                g_dist[tgt * KK + it] = sqrtf(bv);
            }
        }
    } else if (bid < 2048 + 1023) {
        // ---------- posA table ----------
        int dd = bid - 2048;
        float delta = (float)(dd - 511);
        if (t < 8) {
            float freq = expf(-(float)(2 * t) * (9.210340371976184f / 16.0f));
            float ang = delta * freq;
            trig[t]     = cosf(ang);
            trig[8 + t] = sinf(ang);
        }
        __syncthreads();
        float s = 0.f;
#pragma unroll
        for (int j = 0; j < 8; j++) {
            s = fmaf(trig[j],     Wa[(86 + j) * 128 + t], s);
            s = fmaf(trig[8 + j], Wa[(94 + j) * 128 + t], s);
        }
        g_posA[dd * 128 + t] = s;
    } else if (bid < 2048 + 1023 + 1024) {
        // ---------- node precompute: 8 nodes / block ----------
        int n0 = (bid - (2048 + 1023)) * 8;
        if (t < 64) {
            int any = 0;
#pragma unroll
            for (int j = 1; j < 4; j++) any |= (int)xm[4 * t + j];
            unsigned b = __ballot_sync(0xffffffffu, any != 0);
            if (t == 0) s_u8 = (b != 0u) ? 1 : 0;
        }
        __syncthreads();
        int u8 = s_u8;
        for (int m = 0; m < 8; m++) {
            int n = n0 + m;
            int r = t >> 5, c = t & 31;
            semb[m][r][c] = node_emb[n * 128 + t];
            if (t == 0) {
                const float* R = rots + n * 9;
                const float bx0 = -0.525f, by0 = 1.363f, bx2 = 1.526f;
#pragma unroll
                for (int i = 0; i < 3; i++) {
                    float r0 = R[i * 3 + 0], r1 = R[i * 3 + 1];
                    semb[m][1 + i][32 + 0] = r0 * bx0 + r1 * by0;
                    semb[m][1 + i][32 + 1] = 0.f;
                    semb[m][1 + i][32 + 2] = r0 * bx2;
                }
                int xv = u8 ? (int)xm[n] : (int)xm[n * 4];
                int nv = u8 ? (int)nm[n] : (int)nm[n * 4];
                semb[m][0][32] = 0.f;
                semb[m][0][33] = 0.f;
                semb[m][0][34] = (nv && !xv) ? 1.f : 0.f;
            }
        }
        __syncthreads();
        ull acc2[8];
#pragma unroll
        for (int m = 0; m < 8; m++) acc2[m] = 0ull;
        for (int ch = 0; ch < 35; ch++) {
            ull w2 = pk2(Wa[ch * 128 + t], Wa[(35 + ch) * 128 + t]);
#pragma unroll
            for (int m = 0; m < 8; m++) {
                float e0 = semb[m][0][ch];
                acc2[m] = fma2(pk2(e0, e0), w2, acc2[m]);
            }
        }
#pragma unroll
        for (int m = 0; m < 8; m++) {
            float s, tt; upk2(acc2[m], s, tt);
            g_Psrc[(n0 + m) * 128 + t] = s;
            g_Ptgt[(n0 + m) * 128 + t] = tt;
        }
        int c = t & 63, r0 = t >> 6;
        ull v2[8];
#pragma unroll
        for (int m = 0; m < 8; m++) v2[m] = 0ull;
        for (int ch = 0; ch < 35; ch++) {
            float w = Wv[ch * 64 + c];
            ull wd = pk2(w, w);
#pragma unroll
            for (int m = 0; m < 8; m++)
                v2[m] = fma2(pk2(semb[m][r0][ch], semb[m][r0 + 2][ch]), wd, v2[m]);
        }
#pragma unroll
        for (int m = 0; m < 8; m++) {
            float a, b; upk2(v2[m], a, b);
            g_Vnode[(n0 + m) * 256 + t]       = a;
            g_Vnode[(n0 + m) * 256 + 128 + t] = b;
        }
    } else {
        // ---------- rbf lerp table: row dd -> rbf(d_dd) . Wa[70:86] ----------
        int dd = bid - (2048 + 1023 + 1024);
        float dval = (float)dd * (24.0f / (float)TB);
        if (t < 16) {
            float x = (dval - (float)t * (20.0f / 15.0f)) * 0.8f;
            trig[t] = __expf(-x * x);
        }
        __syncthreads();
        float s = 0.f;
#pragma unroll
        for (int j = 0; j < 16; j++)
            s = fmaf(trig[j], Wa[(70 + j) * 128 + t], s);
        g_rbfT[dd * 128 + t] = s;
    }
}

// ================= main kernel: one block per target node ===================
__global__ void __launch_bounds__(128)
k_main(const float* __restrict__ avec,
       const float* __restrict__ Wo,
       const float* __restrict__ Wg,
       const float* __restrict__ W2,
       float* __restrict__ out)
{
    __shared__ __align__(16) float s_part[KK][32];   // 4 partials x 8 heads
    __shared__ __align__(16) float s_agg[256];
    __shared__ float s_alphaT[8][32];                // [head][edge]
    __shared__ float s_y[128];
    __shared__ float s_gate[32];
    __shared__ int   s_src[KK];
    __shared__ int   s_tidx[KK];
    __shared__ float s_frac[KK];
    __shared__ float s_valid[KK];

    int n = blockIdx.x, t = threadIdx.x;
    if (t < KK) {
        int s = g_knn[n * KK + t];
        float d = g_dist[n * KK + t];
        s_src[t] = s;
        s_valid[t] = (isfinite(d) && d > 1e-3f) ? 1.f : 0.f;
        float u = fminf(d * TB_SCALE, (float)(TB - 2) + 0.999f);
        u = fmaxf(u, 0.f);
        int i = (int)u;
        s_tidx[t] = i;
        s_frac[t] = u - (float)i;
    }
    float ptgt = g_Ptgt[n * 128 + t];
    float av = avec[t];                 // a_vec flat: t = h*16+k
    __syncthreads();

    // ---- logits: table-lerp rbf, 2-level shfl, partials to smem ----
#pragma unroll 2
    for (int e = 0; e < KK; e++) {
        int src = s_src[e];
        int ti = s_tidx[e];
        float f = s_frac[e];
        const float* tb = g_rbfT + (size_t)ti * 128 + t;
        float t0 = tb[0];
        float t1 = tb[128];
        float acc = ptgt + g_Psrc[(size_t)src * 128 + t]
                         + g_posA[(size_t)(src - n + 511) * 128 + t];
        acc += fmaf(f, t1 - t0, t0);
        float hd = acc / (1.f + __expf(-acc));       // silu
        float p = hd * av;
        p += __shfl_xor_sync(0xffffffffu, p, 8);
        p += __shfl_xor_sync(0xffffffffu, p, 4);
        if ((t & 15) < 4)
            s_part[e][(t >> 4) * 4 + (t & 3)] = p;   // partial sums (mod-4 classes)
    }
    __syncthreads();

    // ---- softmax (warp 0: 4 lanes per head) ----
    if (t < 32) {
        int h = t >> 2, q = t & 3;
        float lg[8];
        float mx = -1e30f;
        int cnt = 0;
        for (int e = q; e < KK; e += 4, cnt++) {
            float s = s_part[e][h * 4 + 0] + s_part[e][h * 4 + 1]
                    + s_part[e][h * 4 + 2] + s_part[e][h * 4 + 3];
            float l = (s > 0.f) ? s : 0.2f * s;      // leaky_relu 0.2
            l = (s_valid[e] > 0.f) ? l : -1e9f;
            lg[cnt] = l;
            mx = fmaxf(mx, l);
        }
        mx = fmaxf(mx, __shfl_xor_sync(0xffffffffu, mx, 1));
        mx = fmaxf(mx, __shfl_xor_sync(0xffffffffu, mx, 2));
        float den = 0.f;
        cnt = 0;
        for (int e = q; e < KK; e += 4, cnt++) {
            float ex = __expf(lg[cnt] - mx) * s_valid[e];
            s_alphaT[h][e] = ex;
            den += ex;
        }
        den += __shfl_xor_sync(0xffffffffu, den, 1);
        den += __shfl_xor_sync(0xffffffffu, den, 2);
        float inv = 1.f / (den + 1e-9f);
        cnt = 0;
        for (int e = q; e < KK; e += 4)
            s_alphaT[h][e] *= inv;
    }
    __syncthreads();

    // ---- value aggregation: thread owns channel pair 2t (LDG.64) ----
    {
        int off = 2 * t;                  // [0,256)
        int h = (off & 63) >> 3;          // head (same for both channels of pair)
        float a0 = 0.f, a1 = 0.f;
#pragma unroll
        for (int e = 0; e < KK; e++) {
            float al = s_alphaT[h][e];
            float2 v = *reinterpret_cast<const float2*>(
                g_Vnode + (size_t)s_src[e] * 256 + off);
            a0 = fmaf(al, v.x, a0);
            a1 = fmaf(al, v.y, a1);
        }
        s_agg[off] = a0; s_agg[off + 1] = a1;
    }
    __syncthreads();

    // ---- epilogue: y = agg @ Wo ; gate ; out ----
    int r = t >> 5, o = t & 31;
    float y = 0.f;
#pragma unroll
    for (int cc = 0; cc < 64; cc++)
        y = fmaf(s_agg[r * 64 + cc], Wo[cc * 32 + o], y);
    s_y[t] = y;
    __syncthreads();
    if (t < 32) {
        float g = 0.f;
#pragma unroll
        for (int j = 0; j < 32; j++) g = fmaf(s_y[j], Wg[j * 32 + t], g);
        s_gate[t] = g / (1.f + __expf(-g));          // silu gate
    }
    __syncthreads();
    float oo = 0.f;
#pragma unroll
    for (int j = 0; j < 32; j++)
        oo = fmaf(s_y[r * 32 + j] * s_gate[j], W2[j * 32 + o], oo);
    out[n * 128 + t] = oo;
}

// ---------------- launch ----------------
extern "C" void kernel_launch(void* const* d_in, const int* in_sizes, int n_in,
                              void* d_out, int out_size)
{
    const float* rots     = (const float*)d_in[0];
    const float* trans    = (const float*)d_in[1];
    const float* node_emb = (const float*)d_in[2];
    const unsigned char* xm = (const unsigned char*)d_in[4];
    const unsigned char* nm = (const unsigned char*)d_in[5];
    const float* Wa = (const float*)d_in[6];
    const float* av = (const float*)d_in[7];
    const float* Wv = (const float*)d_in[8];
    const float* Wo = (const float*)d_in[9];
    const float* Wg = (const float*)d_in[10];
    const float* W2 = (const float*)d_in[11];
    float* out = (float*)d_out;

    k_prep<<<2048 + 1023 + 1024 + TB, 128>>>(trans, rots, node_emb, xm, nm, Wa, Wv);
    k_main<<<NN, 128>>>(av, Wo, Wg, W2, out);
}

// round 7
// speedup vs baseline: 2.1739x; 1.0245x over previous
#include <cuda_runtime.h>
#include <math.h>

#define NN 8192
#define LL 512
#define KK 30
#define TB 2048                 // rbf table bins over [0,24)
#define TB_SCALE (2048.0f / 24.0f)

typedef unsigned long long ull;

// ---------------- packed f32x2 helpers (used in k_prep only) ----------------
__device__ __forceinline__ ull pk2(float a, float b) {
    ull r; asm("mov.b64 %0, {%1,%2};" : "=l"(r) : "f"(a), "f"(b)); return r;
}
__device__ __forceinline__ void upk2(ull v, float& a, float& b) {
    asm("mov.b64 {%0,%1}, %2;" : "=f"(a), "=f"(b) : "l"(v));
}
__device__ __forceinline__ ull fma2(ull x, ull y, ull a) {
    ull r; asm("fma.rn.f32x2 %0, %1, %2, %3;" : "=l"(r) : "l"(x), "l"(y), "l"(a));
    return r;
}

// ---------------- device scratch ----------------
__device__ int    g_knn [NN * KK];
__device__ float  g_dist[NN * KK];
__device__ float  g_Psrc[NN * 128];
__device__ float  g_Ptgt[NN * 128];
__device__ float  g_Vnode[NN * 256];
__device__ float  g_posA[1023 * 128];
__device__ float2 g_rbfT2[TB * 128];   // {T[dd][c], T[dd+1][c]}

// ================= prep kernel: knn | posA | node | rbf-table ==============
__global__ void k_prep(const float* __restrict__ trans,
                       const float* __restrict__ rots,
                       const float* __restrict__ node_emb,
                       const unsigned char* __restrict__ xm,
                       const unsigned char* __restrict__ nm,
                       const float* __restrict__ Wa,
                       const float* __restrict__ Wv)
{
    __shared__ float sx[LL], sy[LL], sz[LL];
    __shared__ float semb[8][4][36];
    __shared__ float trig[32];
    __shared__ int   s_u8;
    int bid = blockIdx.x, t = threadIdx.x;

    if (bid < 2048) {
        // ---------- kNN: 4 targets / block, warp per target, dual-extract ----
        int g0 = bid * 4;
        int base = (g0 >> 9) << 9;
        for (int i = t; i < LL; i += 128) {
            const float* p = trans + (size_t)(base + i) * 3;
            sx[i] = p[0]; sy[i] = p[1]; sz[i] = p[2];
        }
        __syncthreads();
        int warp = t >> 5, lane = t & 31;
        int tgt = g0 + warp;
        int tl = tgt & 511;
        float px = sx[tl], py = sy[tl], pz = sz[tl];
        float d[16];
#pragma unroll
        for (int q = 0; q < 16; q++) {
            int c = lane + (q << 5);
            float dx = sx[c] - px, dy = sy[c] - py, dz = sz[c] - pz;
            float d2 = dx * dx + dy * dy + dz * dz;
            d[q] = (c == tl) ? 1e30f : d2;
        }
        for (int it = 0; it < 15; it++) {
            // local top-2 of this lane's 16
            float m1 = 1e31f, m2 = 1e31f; int i1 = 0, i2 = 0;
#pragma unroll
            for (int q = 0; q < 16; q++) {
                float v = d[q];
                int c = lane | (q << 5);
                if (v < m1)      { m2 = m1; i2 = i1; m1 = v; i1 = c; }
                else if (v < m2) { m2 = v; i2 = c; }
            }
            // butterfly merge of (top1, top2) pairs with lexicographic tie-break
#pragma unroll
            for (int off = 16; off > 0; off >>= 1) {
                float b1 = __shfl_xor_sync(0xffffffffu, m1, off);
                int   j1 = __shfl_xor_sync(0xffffffffu, i1, off);
                float b2 = __shfl_xor_sync(0xffffffffu, m2, off);
                int   j2 = __shfl_xor_sync(0xffffffffu, i2, off);
                bool bless = (b1 < m1) || (b1 == m1 && j1 < i1);
                float w1 = bless ? b1 : m1;  int wi1 = bless ? j1 : i1;
                float l1 = bless ? m1 : b1;  int li1 = bless ? i1 : j1;
                float c2 = bless ? b2 : m2;  int ci2 = bless ? j2 : i2;
                bool sless = (c2 < l1) || (c2 == l1 && ci2 < li1);
                m1 = w1; i1 = wi1;
                m2 = sless ? c2 : l1;
                i2 = sless ? ci2 : li1;
            }
            // all lanes hold the global two smallest; owners remove
            int q1 = i1 >> 5, q2 = i2 >> 5;
            if (lane == (i1 & 31)) {
#pragma unroll
                for (int q = 0; q < 16; q++) if (q == q1) d[q] = 1e30f;
            }
            if (lane == (i2 & 31)) {
#pragma unroll
                for (int q = 0; q < 16; q++) if (q == q2) d[q] = 1e30f;
            }
            if (lane == 0) {
                g_knn [tgt * KK + 2 * it]     = base + i1;
                g_dist[tgt * KK + 2 * it]     = sqrtf(m1);
                g_knn [tgt * KK + 2 * it + 1] = base + i2;
                g_dist[tgt * KK + 2 * it + 1] = sqrtf(m2);
            }
        }
    } else if (bid < 2048 + 1023) {
        // ---------- posA table ----------
        int dd = bid - 2048;
        float delta = (float)(dd - 511);
        if (t < 8) {
            float freq = expf(-(float)(2 * t) * (9.210340371976184f / 16.0f));
            float ang = delta * freq;
            trig[t]     = cosf(ang);
            trig[8 + t] = sinf(ang);
        }
        __syncthreads();
        float s = 0.f;
#pragma unroll
        for (int j = 0; j < 8; j++) {
            s = fmaf(trig[j],     Wa[(86 + j) * 128 + t], s);
            s = fmaf(trig[8 + j], Wa[(94 + j) * 128 + t], s);
        }
        g_posA[dd * 128 + t] = s;
    } else if (bid < 2048 + 1023 + 1024) {
        // ---------- node precompute: 8 nodes / block ----------
        int n0 = (bid - (2048 + 1023)) * 8;
        if (t < 64) {
            int any = 0;
#pragma unroll
            for (int j = 1; j < 4; j++) any |= (int)xm[4 * t + j];
            unsigned b = __ballot_sync(0xffffffffu, any != 0);
            if (t == 0) s_u8 = (b != 0u) ? 1 : 0;
        }
        __syncthreads();
        int u8 = s_u8;
        for (int m = 0; m < 8; m++) {
            int n = n0 + m;
            int r = t >> 5, c = t & 31;
            semb[m][r][c] = node_emb[n * 128 + t];
            if (t == 0) {
                const float* R = rots + n * 9;
                const float bx0 = -0.525f, by0 = 1.363f, bx2 = 1.526f;
#pragma unroll
                for (int i = 0; i < 3; i++) {
                    float r0 = R[i * 3 + 0], r1 = R[i * 3 + 1];
                    semb[m][1 + i][32 + 0] = r0 * bx0 + r1 * by0;
                    semb[m][1 + i][32 + 1] = 0.f;
                    semb[m][1 + i][32 + 2] = r0 * bx2;
                }
                int xv = u8 ? (int)xm[n] : (int)xm[n * 4];
                int nv = u8 ? (int)nm[n] : (int)nm[n * 4];
                semb[m][0][32] = 0.f;
                semb[m][0][33] = 0.f;
                semb[m][0][34] = (nv && !xv) ? 1.f : 0.f;
            }
        }
        __syncthreads();
        ull acc2[8];
#pragma unroll
        for (int m = 0; m < 8; m++) acc2[m] = 0ull;
        for (int ch = 0; ch < 35; ch++) {
            ull w2 = pk2(Wa[ch * 128 + t], Wa[(35 + ch) * 128 + t]);
#pragma unroll
            for (int m = 0; m < 8; m++) {
                float e0 = semb[m][0][ch];
                acc2[m] = fma2(pk2(e0, e0), w2, acc2[m]);
            }
        }
#pragma unroll
        for (int m = 0; m < 8; m++) {
            float s, tt; upk2(acc2[m], s, tt);
            g_Psrc[(n0 + m) * 128 + t] = s;
            g_Ptgt[(n0 + m) * 128 + t] = tt;
        }
        int c = t & 63, r0 = t >> 6;
        ull v2[8];
#pragma unroll
        for (int m = 0; m < 8; m++) v2[m] = 0ull;
        for (int ch = 0; ch < 35; ch++) {
            float w = Wv[ch * 64 + c];
            ull wd = pk2(w, w);
#pragma unroll
            for (int m = 0; m < 8; m++)
                v2[m] = fma2(pk2(semb[m][r0][ch], semb[m][r0 + 2][ch]), wd, v2[m]);
        }
#pragma unroll
        for (int m = 0; m < 8; m++) {
            float a, b; upk2(v2[m], a, b);
            g_Vnode[(n0 + m) * 256 + t]       = a;
            g_Vnode[(n0 + m) * 256 + 128 + t] = b;
        }
    } else {
        // ---------- rbf lerp table (pairs): rows dd and dd+1 ----------
        int dd = bid - (2048 + 1023 + 1024);
        if (t < 32) {
            int j = t & 15;
            float dval = (float)(dd + (t >> 4)) * (24.0f / (float)TB);
            float x = (dval - (float)j * (20.0f / 15.0f)) * 0.8f;
            trig[t] = __expf(-x * x);
        }
        __syncthreads();
        float s0 = 0.f, s1 = 0.f;
#pragma unroll
        for (int j = 0; j < 16; j++) {
            float w = Wa[(70 + j) * 128 + t];
            s0 = fmaf(trig[j],      w, s0);
            s1 = fmaf(trig[16 + j], w, s1);
        }
        g_rbfT2[dd * 128 + t] = make_float2(s0, s1);
    }
}

// ================= main kernel: one block per target node ===================
__global__ void __launch_bounds__(128)
k_main(const float* __restrict__ avec,
       const float* __restrict__ Wo,
       const float* __restrict__ Wg,
       const float* __restrict__ W2,
       float* __restrict__ out)
{
    __shared__ __align__(16) float s_lpart[KK][32];   // 4 partials x 8 heads
    __shared__ __align__(16) float s_aggT[64][4];     // transposed aggregate
    __shared__ __align__(16) float4 s_ep[4][32];      // epilogue partials
    __shared__ __align__(16) float4 s_ygT[32];        // gated y, transposed
    __shared__ float s_alphaT[8][32];                 // [head][edge]
    __shared__ float s_y0[32];
    __shared__ int   s_src[KK];
    __shared__ int   s_tidx[KK];
    __shared__ float s_frac[KK];
    __shared__ float s_valid[KK];

    int n = blockIdx.x, t = threadIdx.x;
    if (t < KK) {
        int s = g_knn[n * KK + t];
        float d = g_dist[n * KK + t];
        s_src[t] = s;
        s_valid[t] = (isfinite(d) && d > 1e-3f) ? 1.f : 0.f;
        float u = fminf(d * TB_SCALE, (float)(TB - 2) + 0.999f);
        u = fmaxf(u, 0.f);
        int i = (int)u;
        s_tidx[t] = i;
        s_frac[t] = u - (float)i;
    }
    float ptgt = g_Ptgt[n * 128 + t];
    float av = avec[t];                 // a_vec flat: t = h*16+k
    __syncthreads();

    // ---- logits: table-lerp rbf (float2), 2-level shfl, partials ----
#pragma unroll 2
    for (int e = 0; e < KK; e++) {
        int src = s_src[e];
        float2 tv = g_rbfT2[(size_t)s_tidx[e] * 128 + t];
        float f = s_frac[e];
        float acc = ptgt + g_Psrc[(size_t)src * 128 + t]
                         + g_posA[(size_t)(src - n + 511) * 128 + t];
        acc += fmaf(f, tv.y - tv.x, tv.x);
        float hd = acc / (1.f + __expf(-acc));       // silu
        float p = hd * av;
        p += __shfl_xor_sync(0xffffffffu, p, 8);
        p += __shfl_xor_sync(0xffffffffu, p, 4);
        if ((t & 15) < 4)
            s_lpart[e][(t >> 4) * 4 + (t & 3)] = p;
    }
    __syncthreads();

    // ---- softmax (warp 0: 4 lanes per head) ----
    if (t < 32) {
        int h = t >> 2, q = t & 3;
        float lg[8];
        float mx = -1e30f;
        int cnt = 0;
        for (int e = q; e < KK; e += 4, cnt++) {
            float s = s_lpart[e][h * 4 + 0] + s_lpart[e][h * 4 + 1]
                    + s_lpart[e][h * 4 + 2] + s_lpart[e][h * 4 + 3];
            float l = (s > 0.f) ? s : 0.2f * s;      // leaky_relu 0.2
            l = (s_valid[e] > 0.f) ? l : -1e9f;
            lg[cnt] = l;
            mx = fmaxf(mx, l);
        }
        mx = fmaxf(mx, __shfl_xor_sync(0xffffffffu, mx, 1));
        mx = fmaxf(mx, __shfl_xor_sync(0xffffffffu, mx, 2));
        float den = 0.f;
        cnt = 0;
        for (int e = q; e < KK; e += 4, cnt++) {
            float ex = __expf(lg[cnt] - mx) * s_valid[e];
            s_alphaT[h][e] = ex;
            den += ex;
        }
        den += __shfl_xor_sync(0xffffffffu, den, 1);
        den += __shfl_xor_sync(0xffffffffu, den, 2);
        float inv = 1.f / (den + 1e-9f);
        for (int e = q; e < KK; e += 4)
            s_alphaT[h][e] *= inv;
    }
    __syncthreads();

    // ---- value aggregation: thread owns channels (t, t+128) ----
    {
        int cc = t & 63, rr = t >> 6;     // channels (rr,cc) and (rr+2,cc)
        int h = cc >> 3;
        float a0 = 0.f, a1 = 0.f;
#pragma unroll
        for (int e = 0; e < KK; e++) {
            float al = s_alphaT[h][e];
            const float* vp = g_Vnode + (size_t)s_src[e] * 256;
            a0 = fmaf(al, vp[t],       a0);
            a1 = fmaf(al, vp[t + 128], a1);
        }
        s_aggT[cc][rr]     = a0;
        s_aggT[cc][rr + 2] = a1;
    }
    __syncthreads();

    // ---- epilogue: y = agg @ Wo (4 outputs/thread), gate, W2 ----
    int o = t & 31, s = t >> 5;
    const float4* aggT4 = reinterpret_cast<const float4*>(s_aggT);
    float4 acc4 = make_float4(0.f, 0.f, 0.f, 0.f);
#pragma unroll
    for (int i = 0; i < 16; i++) {
        int cc = s * 16 + i;
        float4 a4 = aggT4[cc];
        float w = Wo[cc * 32 + o];
        acc4.x = fmaf(a4.x, w, acc4.x);
        acc4.y = fmaf(a4.y, w, acc4.y);
        acc4.z = fmaf(a4.z, w, acc4.z);
        acc4.w = fmaf(a4.w, w, acc4.w);
    }
    s_ep[s][o] = acc4;
    __syncthreads();
    float4 y4;
    if (t < 32) {
        float4 p0 = s_ep[0][t], p1 = s_ep[1][t], p2 = s_ep[2][t], p3 = s_ep[3][t];
        y4.x = p0.x + p1.x + p2.x + p3.x;
        y4.y = p0.y + p1.y + p2.y + p3.y;
        y4.z = p0.z + p1.z + p2.z + p3.z;
        y4.w = p0.w + p1.w + p2.w + p3.w;
        s_y0[t] = y4.x;
    }
    __syncthreads();
    if (t < 32) {
        float g = 0.f;
#pragma unroll
        for (int j = 0; j < 32; j++) g = fmaf(s_y0[j], Wg[j * 32 + t], g);
        g = g / (1.f + __expf(-g));       // silu gate
        y4.x *= g; y4.y *= g; y4.z *= g; y4.w *= g;
        s_ygT[t] = y4;                    // [j] -> {yg[0][j]..yg[3][j]}
    }
    __syncthreads();
    float4 acc2 = make_float4(0.f, 0.f, 0.f, 0.f);
#pragma unroll
    for (int i = 0; i < 8; i++) {
        int j = s * 8 + i;
        float4 a4 = s_ygT[j];
        float w = W2[j * 32 + o];
        acc2.x = fmaf(a4.x, w, acc2.x);
        acc2.y = fmaf(a4.y, w, acc2.y);
        acc2.z = fmaf(a4.z, w, acc2.z);
        acc2.w = fmaf(a4.w, w, acc2.w);
    }
    s_ep[s][o] = acc2;
    __syncthreads();
    if (t < 32) {
        float4 p0 = s_ep[0][t], p1 = s_ep[1][t], p2 = s_ep[2][t], p3 = s_ep[3][t];
        float* op = out + (size_t)n * 128;
        op[t]      = p0.x + p1.x + p2.x + p3.x;
        op[t + 32] = p0.y + p1.y + p2.y + p3.y;
        op[t + 64] = p0.z + p1.z + p2.z + p3.z;
        op[t + 96] = p0.w + p1.w + p2.w + p3.w;
    }
}

// ---------------- launch ----------------
extern "C" void kernel_launch(void* const* d_in, const int* in_sizes, int n_in,
                              void* d_out, int out_size)
{
    const float* rots     = (const float*)d_in[0];
    const float* trans    = (const float*)d_in[1];
    const float* node_emb = (const float*)d_in[2];
    const unsigned char* xm = (const unsigned char*)d_in[4];
    const unsigned char* nm = (const unsigned char*)d_in[5];
    const float* Wa = (const float*)d_in[6];
    const float* av = (const float*)d_in[7];
    const float* Wv = (const float*)d_in[8];
    const float* Wo = (const float*)d_in[9];
    const float* Wg = (const float*)d_in[10];
    const float* W2 = (const float*)d_in[11];
    float* out = (float*)d_out;

    k_prep<<<2048 + 1023 + 1024 + TB, 128>>>(trans, rots, node_emb, xm, nm, Wa, Wv);
    k_main<<<NN, 128>>>(av, Wo, Wg, W2, out);
}

// round 8
// speedup vs baseline: 2.2627x; 1.0409x over previous
#include <cuda_runtime.h>
#include <math.h>
#include <stddef.h>

#define NN 8192
#define LL 512
#define KK 30
#define TB 2048                 // rbf table bins over [0,24)
#define TB_SCALE (2048.0f / 24.0f)

typedef unsigned long long ull;

// ---------------- packed f32x2 helpers (used in k_aux only) ----------------
__device__ __forceinline__ ull pk2(float a, float b) {
    ull r; asm("mov.b64 %0, {%1,%2};" : "=l"(r) : "f"(a), "f"(b)); return r;
}
__device__ __forceinline__ void upk2(ull v, float& a, float& b) {
    asm("mov.b64 {%0,%1}, %2;" : "=f"(a), "=f"(b) : "l"(v));
}
__device__ __forceinline__ ull fma2(ull x, ull y, ull a) {
    ull r; asm("fma.rn.f32x2 %0, %1, %2, %3;" : "=l"(r) : "l"(x), "l"(y), "l"(a));
    return r;
}

// ---------------- device scratch ----------------
__device__ int    g_knn [NN * KK];
__device__ float  g_dist[NN * KK];
__device__ float  g_Psrc[NN * 128];
__device__ float  g_Ptgt[NN * 128];
__device__ float2 g_Vnode2[NN * 128];  // {rows (r, r+2)} interleaved
__device__ float  g_posA[1023 * 128];
__device__ float2 g_rbfT2[TB * 128];   // {T[dd][c], T[dd+1][c]}

// ================= kNN kernel: sort + redux merge-extraction ================
__global__ void k_knn(const float* __restrict__ trans)
{
    __shared__ float sx[LL], sy[LL], sz[LL];
    __shared__ unsigned skey[4 * 16 * 32];
    __shared__ int      sidx[4 * 16 * 32];
    int t = threadIdx.x;
    int g0 = blockIdx.x * 4;          // 4 targets per block (warp each)
    int base = (g0 >> 9) << 9;
    for (int i = t; i < LL; i += 128) {
        const float* p = trans + (size_t)(base + i) * 3;
        sx[i] = p[0]; sy[i] = p[1]; sz[i] = p[2];
    }
    __syncthreads();
    int warp = t >> 5, lane = t & 31;
    int tgt = g0 + warp;
    int tl = tgt & 511;
    float px = sx[tl], py = sy[tl], pz = sz[tl];

    unsigned key[16]; int idx[16];
#pragma unroll
    for (int q = 0; q < 16; q++) {
        int c = lane + (q << 5);
        float dx = sx[c] - px, dy = sy[c] - py, dz = sz[c] - pz;
        float d2 = dx * dx + dy * dy + dz * dz;
        if (c == tl) d2 = 1e30f;      // exclude self
        key[q] = __float_as_uint(d2); // positive floats: uint order == float order
        idx[q] = c;
    }
    // Batcher odd-even mergesort, ascending by (key, idx)
#pragma unroll
    for (int p = 1; p < 16; p <<= 1) {
#pragma unroll
        for (int k = p; k >= 1; k >>= 1) {
#pragma unroll
            for (int j = k % p; j + k < 16; j += 2 * k) {
#pragma unroll
                for (int i = 0; i < k; i++) {
                    int a = i + j, b = i + j + k;
                    if (b < 16 && (a / (2 * p)) == (b / (2 * p))) {
                        bool sw = (key[a] > key[b]) ||
                                  (key[a] == key[b] && idx[a] > idx[b]);
                        unsigned ka = sw ? key[b] : key[a];
                        unsigned kb = sw ? key[a] : key[b];
                        int ia = sw ? idx[b] : idx[a];
                        int ib = sw ? idx[a] : idx[b];
                        key[a] = ka; key[b] = kb; idx[a] = ia; idx[b] = ib;
                    }
                }
            }
        }
    }
    // spill sorted tail to smem (head stays in regs); lane-indexed: conflict-free
    int lb = warp * 512 + lane;
#pragma unroll
    for (int q = 1; q < 16; q++) {
        skey[lb + q * 32] = key[q];
        sidx[lb + q * 32] = idx[q];
    }
    unsigned ck = key[0]; int ci = idx[0];
    int ptr = 1;
    for (int it = 0; it < KK; it++) {
        unsigned mv = __reduce_min_sync(0xffffffffu, ck);
        unsigned ti = (ck == mv) ? (unsigned)ci : 0xffffffffu;
        unsigned mi = __reduce_min_sync(0xffffffffu, ti);  // smallest idx among ties
        if (lane == 0) {
            g_knn [tgt * KK + it] = base + (int)mi;
            g_dist[tgt * KK + it] = sqrtf(__uint_as_float(mv));
        }
        if (ck == mv && (unsigned)ci == mi) {      // unique owner advances
            if (ptr < 16) {
                ck = skey[lb + ptr * 32];
                ci = sidx[lb + ptr * 32];
                ptr++;
            } else ck = 0xffffffffu;
        }
    }
}

// ================= aux kernel: posA | node | rbf-table ======================
__global__ void k_aux(const float* __restrict__ rots,
                      const float* __restrict__ node_emb,
                      const unsigned char* __restrict__ xm,
                      const unsigned char* __restrict__ nm,
                      const float* __restrict__ Wa,
                      const float* __restrict__ Wv)
{
    __shared__ float semb[8][4][36];
    __shared__ float trig[16];
    __shared__ int   s_u8;
    int bid = blockIdx.x, t = threadIdx.x;

    if (bid < 1023) {
        // ---------- posA table ----------
        int dd = bid;
        float delta = (float)(dd - 511);
        if (t < 8) {
            float freq = expf(-(float)(2 * t) * (9.210340371976184f / 16.0f));
            float ang = delta * freq;
            trig[t]     = cosf(ang);
            trig[8 + t] = sinf(ang);
        }
        __syncthreads();
        float s = 0.f;
#pragma unroll
        for (int j = 0; j < 8; j++) {
            s = fmaf(trig[j],     Wa[(86 + j) * 128 + t], s);
            s = fmaf(trig[8 + j], Wa[(94 + j) * 128 + t], s);
        }
        g_posA[dd * 128 + t] = s;
    } else if (bid < 1023 + 1024) {
        // ---------- node precompute: 8 nodes / block ----------
        int n0 = (bid - 1023) * 8;
        if (t < 64) {
            int any = 0;
#pragma unroll
            for (int j = 1; j < 4; j++) any |= (int)xm[4 * t + j];
            unsigned b = __ballot_sync(0xffffffffu, any != 0);
            if (t == 0) s_u8 = (b != 0u) ? 1 : 0;
        }
        __syncthreads();
        int u8 = s_u8;
        for (int m = 0; m < 8; m++) {
            int n = n0 + m;
            int r = t >> 5, c = t & 31;
            semb[m][r][c] = node_emb[n * 128 + t];
            if (t == 0) {
                const float* R = rots + n * 9;
                const float bx0 = -0.525f, by0 = 1.363f, bx2 = 1.526f;
#pragma unroll
                for (int i = 0; i < 3; i++) {
                    float r0 = R[i * 3 + 0], r1 = R[i * 3 + 1];
                    semb[m][1 + i][32 + 0] = r0 * bx0 + r1 * by0;
                    semb[m][1 + i][32 + 1] = 0.f;
                    semb[m][1 + i][32 + 2] = r0 * bx2;
                }
                int xv = u8 ? (int)xm[n] : (int)xm[n * 4];
                int nv = u8 ? (int)nm[n] : (int)nm[n * 4];
                semb[m][0][32] = 0.f;
                semb[m][0][33] = 0.f;
                semb[m][0][34] = (nv && !xv) ? 1.f : 0.f;
            }
        }
        __syncthreads();
        ull acc2[8];
#pragma unroll
        for (int m = 0; m < 8; m++) acc2[m] = 0ull;
        for (int ch = 0; ch < 35; ch++) {
            ull w2 = pk2(Wa[ch * 128 + t], Wa[(35 + ch) * 128 + t]);
#pragma unroll
            for (int m = 0; m < 8; m++) {
                float e0 = semb[m][0][ch];
                acc2[m] = fma2(pk2(e0, e0), w2, acc2[m]);
            }
        }
#pragma unroll
        for (int m = 0; m < 8; m++) {
            float s, tt; upk2(acc2[m], s, tt);
            g_Psrc[(n0 + m) * 128 + t] = s;
            g_Ptgt[(n0 + m) * 128 + t] = tt;
        }
        int c = t & 63, r0 = t >> 6;
        ull v2[8];
#pragma unroll
        for (int m = 0; m < 8; m++) v2[m] = 0ull;
        for (int ch = 0; ch < 35; ch++) {
            float w = Wv[ch * 64 + c];
            ull wd = pk2(w, w);
#pragma unroll
            for (int m = 0; m < 8; m++)
                v2[m] = fma2(pk2(semb[m][r0][ch], semb[m][r0 + 2][ch]), wd, v2[m]);
        }
#pragma unroll
        for (int m = 0; m < 8; m++) {
            float a, b; upk2(v2[m], a, b);
            g_Vnode2[(n0 + m) * 128 + t] = make_float2(a, b);
        }
    } else {
        // ---------- rbf lerp table: one row/block; fill own .x and prev .y ---
        int dd = bid - (1023 + 1024);      // 0..TB-1
        float dval = (float)dd * (24.0f / (float)TB);
        if (t < 16) {
            float x = (dval - (float)t * (20.0f / 15.0f)) * 0.8f;
            trig[t] = __expf(-x * x);
        }
        __syncthreads();
        float s = 0.f;
#pragma unroll
        for (int j = 0; j < 16; j++)
            s = fmaf(trig[j], Wa[(70 + j) * 128 + t], s);
        if (dd < TB - 1) g_rbfT2[dd * 128 + t].x = s;
        if (dd >= 1)     g_rbfT2[(dd - 1) * 128 + t].y = s;
    }
}

// ================= main kernel: one block per target node ===================
__global__ void __launch_bounds__(128)
k_main(const float* __restrict__ avec,
       const float* __restrict__ Wo,
       const float* __restrict__ Wg,
       const float* __restrict__ W2,
       float* __restrict__ out)
{
    __shared__ __align__(16) float s_lpart[KK][32];   // 4 partials x 8 heads
    __shared__ __align__(16) float s_aggT[64][4];     // transposed aggregate
    __shared__ __align__(16) float4 s_ep[4][32];      // epilogue partials
    __shared__ __align__(16) float4 s_ygT[32];        // gated y, transposed
    __shared__ float s_alphaT[8][32];                 // [head][edge]
    __shared__ float s_y0[32];
    __shared__ int   s_off[KK];                       // src * 128
    __shared__ int   s_tidx[KK];
    __shared__ float s_frac[KK];
    __shared__ float s_valid[KK];

    int n = blockIdx.x, t = threadIdx.x;
    if (t < KK) {
        int s = g_knn[n * KK + t];
        float d = g_dist[n * KK + t];
        s_off[t] = s << 7;
        s_valid[t] = (isfinite(d) && d > 1e-3f) ? 1.f : 0.f;
        float u = fminf(d * TB_SCALE, (float)(TB - 2) + 0.999f);
        u = fmaxf(u, 0.f);
        int i = (int)u;
        s_tidx[t] = i;
        s_frac[t] = u - (float)i;
    }
    float ptgt = g_Ptgt[n * 128 + t];
    float av = avec[t];                 // a_vec flat: t = h*16+k
    const float* psrcB = g_Psrc + t;
    const float* posAB = g_posA + (ptrdiff_t)(511 - n) * 128 + t;
    __syncthreads();

    // ---- logits: shared row-offset gathers + table-lerp rbf ----
#pragma unroll 2
    for (int e = 0; e < KK; e++) {
        int off = s_off[e];
        float2 tv = g_rbfT2[((size_t)s_tidx[e] << 7) + t];
        float acc = ptgt + psrcB[off] + posAB[off];
        acc = fmaf(s_frac[e], tv.y - tv.x, acc + tv.x);
        float sig = __fdividef(1.f, 1.f + __expf(-acc));
        float p = acc * sig * av;                    // silu * a_vec
        p += __shfl_xor_sync(0xffffffffu, p, 8);
        p += __shfl_xor_sync(0xffffffffu, p, 4);
        if ((t & 15) < 4)
            s_lpart[e][(t >> 4) * 4 + (t & 3)] = p;
    }
    __syncthreads();

    // ---- softmax (warp 0: 4 lanes per head) ----
    if (t < 32) {
        int h = t >> 2, q = t & 3;
        float lg[8];
        float mx = -1e30f;
        int cnt = 0;
        for (int e = q; e < KK; e += 4, cnt++) {
            float s = s_lpart[e][h * 4 + 0] + s_lpart[e][h * 4 + 1]
                    + s_lpart[e][h * 4 + 2] + s_lpart[e][h * 4 + 3];
            float l = (s > 0.f) ? s : 0.2f * s;      // leaky_relu 0.2
            l = (s_valid[e] > 0.f) ? l : -1e9f;
            lg[cnt] = l;
            mx = fmaxf(mx, l);
        }
        mx = fmaxf(mx, __shfl_xor_sync(0xffffffffu, mx, 1));
        mx = fmaxf(mx, __shfl_xor_sync(0xffffffffu, mx, 2));
        float den = 0.f;
        cnt = 0;
        for (int e = q; e < KK; e += 4, cnt++) {
            float ex = __expf(lg[cnt] - mx) * s_valid[e];
            s_alphaT[h][e] = ex;
            den += ex;
        }
        den += __shfl_xor_sync(0xffffffffu, den, 1);
        den += __shfl_xor_sync(0xffffffffu, den, 2);
        float inv = __fdividef(1.f, den + 1e-9f);
        for (int e = q; e < KK; e += 4)
            s_alphaT[h][e] *= inv;
    }
    __syncthreads();

    // ---- value aggregation: interleaved float2 (rows rr, rr+2) ----
    {
        int cc = t & 63, rr = t >> 6;
        int h = cc >> 3;
        float a0 = 0.f, a1 = 0.f;
#pragma unroll
        for (int e = 0; e < KK; e++) {
            float al = s_alphaT[h][e];
            float2 v = g_Vnode2[s_off[e] + t];
            a0 = fmaf(al, v.x, a0);
            a1 = fmaf(al, v.y, a1);
        }
        s_aggT[cc][rr]     = a0;
        s_aggT[cc][rr + 2] = a1;
    }
    __syncthreads();

    // ---- epilogue: y = agg @ Wo (4 outputs/thread), gate, W2 ----
    int o = t & 31, s = t >> 5;
    const float4* aggT4 = reinterpret_cast<const float4*>(s_aggT);
    float4 acc4 = make_float4(0.f, 0.f, 0.f, 0.f);
#pragma unroll
    for (int i = 0; i < 16; i++) {
        int cc = s * 16 + i;
        float4 a4 = aggT4[cc];
        float w = Wo[cc * 32 + o];
        acc4.x = fmaf(a4.x, w, acc4.x);
        acc4.y = fmaf(a4.y, w, acc4.y);
        acc4.z = fmaf(a4.z, w, acc4.z);
        acc4.w = fmaf(a4.w, w, acc4.w);
    }
    s_ep[s][o] = acc4;
    __syncthreads();
    float4 y4;
    if (t < 32) {
        float4 p0 = s_ep[0][t], p1 = s_ep[1][t], p2 = s_ep[2][t], p3 = s_ep[3][t];
        y4.x = p0.x + p1.x + p2.x + p3.x;
        y4.y = p0.y + p1.y + p2.y + p3.y;
        y4.z = p0.z + p1.z + p2.z + p3.z;
        y4.w = p0.w + p1.w + p2.w + p3.w;
        s_y0[t] = y4.x;
    }
    __syncthreads();
    if (t < 32) {
        float g = 0.f;
#pragma unroll
        for (int j = 0; j < 32; j++) g = fmaf(s_y0[j], Wg[j * 32 + t], g);
        g = g * __fdividef(1.f, 1.f + __expf(-g));   // silu gate
        y4.x *= g; y4.y *= g; y4.z *= g; y4.w *= g;
        s_ygT[t] = y4;
    }
    __syncthreads();
    float4 acc2 = make_float4(0.f, 0.f, 0.f, 0.f);
#pragma unroll
    for (int i = 0; i < 8; i++) {
        int j = s * 8 + i;
        float4 a4 = s_ygT[j];
        float w = W2[j * 32 + o];
        acc2.x = fmaf(a4.x, w, acc2.x);
        acc2.y = fmaf(a4.y, w, acc2.y);
        acc2.z = fmaf(a4.z, w, acc2.z);
        acc2.w = fmaf(a4.w, w, acc2.w);
    }
    s_ep[s][o] = acc2;
    __syncthreads();
    if (t < 32) {
        float4 p0 = s_ep[0][t], p1 = s_ep[1][t], p2 = s_ep[2][t], p3 = s_ep[3][t];
        float* op = out + (size_t)n * 128;
        op[t]      = p0.x + p1.x + p2.x + p3.x;
        op[t + 32] = p0.y + p1.y + p2.y + p3.y;
        op[t + 64] = p0.z + p1.z + p2.z + p3.z;
        op[t + 96] = p0.w + p1.w + p2.w + p3.w;
    }
}

// ---------------- launch: fork aux || knn, join, main ----------------
extern "C" void kernel_launch(void* const* d_in, const int* in_sizes, int n_in,
                              void* d_out, int out_size)
{
    const float* rots     = (const float*)d_in[0];
    const float* trans    = (const float*)d_in[1];
    const float* node_emb = (const float*)d_in[2];
    const unsigned char* xm = (const unsigned char*)d_in[4];
    const unsigned char* nm = (const unsigned char*)d_in[5];
    const float* Wa = (const float*)d_in[6];
    const float* av = (const float*)d_in[7];
    const float* Wv = (const float*)d_in[8];
    const float* Wo = (const float*)d_in[9];
    const float* Wg = (const float*)d_in[10];
    const float* W2 = (const float*)d_in[11];
    float* out = (float*)d_out;

    cudaStream_t s2;
    cudaStreamCreateWithFlags(&s2, cudaStreamNonBlocking);
    cudaEvent_t evFork, evJoin;
    cudaEventCreateWithFlags(&evFork, cudaEventDisableTiming);
    cudaEventCreateWithFlags(&evJoin, cudaEventDisableTiming);

    cudaEventRecord(evFork, 0);                 // fork from legacy stream
    cudaStreamWaitEvent(s2, evFork, 0);
    k_aux<<<1023 + 1024 + TB, 128, 0, s2>>>(rots, node_emb, xm, nm, Wa, Wv);
    cudaEventRecord(evJoin, s2);

    k_knn<<<NN / 4, 128>>>(trans);              // overlaps with k_aux

    cudaStreamWaitEvent(0, evJoin, 0);          // join
    k_main<<<NN, 128>>>(av, Wo, Wg, W2, out);

    cudaEventDestroy(evFork);
    cudaEventDestroy(evJoin);
    cudaStreamDestroy(s2);
}

// round 9
// speedup vs baseline: 2.2647x; 1.0009x over previous
#include <cuda_runtime.h>
#include <math.h>
#include <stddef.h>

#define NN 8192
#define LL 512
#define KK 30
#define TB 2048                 // rbf table bins over [0,24)
#define TB_SCALE (2048.0f / 24.0f)

typedef unsigned long long ull;

// ---------------- packed f32x2 helpers (used in prep only) ----------------
__device__ __forceinline__ ull pk2(float a, float b) {
    ull r; asm("mov.b64 %0, {%1,%2};" : "=l"(r) : "f"(a), "f"(b)); return r;
}
__device__ __forceinline__ void upk2(ull v, float& a, float& b) {
    asm("mov.b64 {%0,%1}, %2;" : "=f"(a), "=f"(b) : "l"(v));
}
__device__ __forceinline__ ull fma2(ull x, ull y, ull a) {
    ull r; asm("fma.rn.f32x2 %0, %1, %2, %3;" : "=l"(r) : "l"(x), "l"(y), "l"(a));
    return r;
}

// ---------------- device scratch ----------------
__device__ int    g_knn [NN * KK];
__device__ float  g_dist[NN * KK];
__device__ float  g_Psrc[NN * 128];
__device__ float  g_Ptgt[NN * 128];
__device__ float2 g_Vnode2[NN * 128];  // {rows (r, r+2)} interleaved
__device__ float  g_posA[1023 * 128];
__device__ float2 g_rbfT2[TB * 128];   // {T[dd][c], T[dd+1][c]}

// ============ merged prep: knn | posA | node | rbf-table by blockIdx ========
__global__ void k_prep(const float* __restrict__ trans,
                       const float* __restrict__ rots,
                       const float* __restrict__ node_emb,
                       const unsigned char* __restrict__ xm,
                       const unsigned char* __restrict__ nm,
                       const float* __restrict__ Wa,
                       const float* __restrict__ Wv)
{
    __shared__ float sbufA[LL];             // knn: sx | aux reuse
    __shared__ float sbufB[LL];
    __shared__ float sbufC[LL];
    __shared__ unsigned skey[4 * 16 * 32];
    __shared__ int      sidx[4 * 16 * 32];
    __shared__ float semb[8][4][36];
    __shared__ float trig[16];
    __shared__ int   s_u8;
    int bid = blockIdx.x, t = threadIdx.x;

    if (bid < 2048) {
        // ---------- kNN: 4 targets/block, warp each; sort + redux extract ----
        float* sx = sbufA; float* sy = sbufB; float* sz = sbufC;
        int g0 = bid * 4;
        int base = (g0 >> 9) << 9;
        for (int i = t; i < LL; i += 128) {
            const float* p = trans + (size_t)(base + i) * 3;
            sx[i] = p[0]; sy[i] = p[1]; sz[i] = p[2];
        }
        __syncthreads();
        int warp = t >> 5, lane = t & 31;
        int tgt = g0 + warp;
        int tl = tgt & 511;
        float px = sx[tl], py = sy[tl], pz = sz[tl];

        unsigned key[16]; int idx[16];
#pragma unroll
        for (int q = 0; q < 16; q++) {
            int c = lane + (q << 5);
            float dx = sx[c] - px, dy = sy[c] - py, dz = sz[c] - pz;
            float d2 = dx * dx + dy * dy + dz * dz;
            if (c == tl) d2 = 1e30f;
            key[q] = __float_as_uint(d2);
            idx[q] = c;
        }
        // Batcher odd-even mergesort, ascending by (key, idx)
#pragma unroll
        for (int p = 1; p < 16; p <<= 1) {
#pragma unroll
            for (int k = p; k >= 1; k >>= 1) {
#pragma unroll
                for (int j = k % p; j + k < 16; j += 2 * k) {
#pragma unroll
                    for (int i = 0; i < k; i++) {
                        int a = i + j, b = i + j + k;
                        if (b < 16 && (a / (2 * p)) == (b / (2 * p))) {
                            bool sw = (key[a] > key[b]) ||
                                      (key[a] == key[b] && idx[a] > idx[b]);
                            unsigned ka = sw ? key[b] : key[a];
                            unsigned kb = sw ? key[a] : key[b];
                            int ia = sw ? idx[b] : idx[a];
                            int ib = sw ? idx[a] : idx[b];
                            key[a] = ka; key[b] = kb; idx[a] = ia; idx[b] = ib;
                        }
                    }
                }
            }
        }
        int lb = warp * 512 + lane;
#pragma unroll
        for (int q = 1; q < 16; q++) {
            skey[lb + q * 32] = key[q];
            sidx[lb + q * 32] = idx[q];
        }
        unsigned ck = key[0]; int ci = idx[0];
        int ptr = 1;
        for (int it = 0; it < KK; it++) {
            unsigned mv = __reduce_min_sync(0xffffffffu, ck);
            unsigned ti = (ck == mv) ? (unsigned)ci : 0xffffffffu;
            unsigned mi = __reduce_min_sync(0xffffffffu, ti);
            if (lane == 0) {
                g_knn [tgt * KK + it] = base + (int)mi;
                g_dist[tgt * KK + it] = sqrtf(__uint_as_float(mv));
            }
            if (ck == mv && (unsigned)ci == mi) {
                if (ptr < 16) {
                    ck = skey[lb + ptr * 32];
                    ci = sidx[lb + ptr * 32];
                    ptr++;
                } else ck = 0xffffffffu;
            }
        }
    } else if (bid < 2048 + 1023) {
        // ---------- posA table ----------
        int dd = bid - 2048;
        float delta = (float)(dd - 511);
        if (t < 8) {
            float freq = expf(-(float)(2 * t) * (9.210340371976184f / 16.0f));
            float ang = delta * freq;
            trig[t]     = cosf(ang);
            trig[8 + t] = sinf(ang);
        }
        __syncthreads();
        float s = 0.f;
#pragma unroll
        for (int j = 0; j < 8; j++) {
            s = fmaf(trig[j],     Wa[(86 + j) * 128 + t], s);
            s = fmaf(trig[8 + j], Wa[(94 + j) * 128 + t], s);
        }
        g_posA[dd * 128 + t] = s;
    } else if (bid < 2048 + 1023 + 1024) {
        // ---------- node precompute: 8 nodes / block ----------
        int n0 = (bid - (2048 + 1023)) * 8;
        if (t < 64) {
            int any = 0;
#pragma unroll
            for (int j = 1; j < 4; j++) any |= (int)xm[4 * t + j];
            unsigned b = __ballot_sync(0xffffffffu, any != 0);
            if (t == 0) s_u8 = (b != 0u) ? 1 : 0;
        }
        __syncthreads();
        int u8 = s_u8;
        for (int m = 0; m < 8; m++) {
            int n = n0 + m;
            int r = t >> 5, c = t & 31;
            semb[m][r][c] = node_emb[n * 128 + t];
            if (t == 0) {
                const float* R = rots + n * 9;
                const float bx0 = -0.525f, by0 = 1.363f, bx2 = 1.526f;
#pragma unroll
                for (int i = 0; i < 3; i++) {
                    float r0 = R[i * 3 + 0], r1 = R[i * 3 + 1];
                    semb[m][1 + i][32 + 0] = r0 * bx0 + r1 * by0;
                    semb[m][1 + i][32 + 1] = 0.f;
                    semb[m][1 + i][32 + 2] = r0 * bx2;
                }
                int xv = u8 ? (int)xm[n] : (int)xm[n * 4];
                int nv = u8 ? (int)nm[n] : (int)nm[n * 4];
                semb[m][0][32] = 0.f;
                semb[m][0][33] = 0.f;
                semb[m][0][34] = (nv && !xv) ? 1.f : 0.f;
            }
        }
        __syncthreads();
        ull acc2[8];
#pragma unroll
        for (int m = 0; m < 8; m++) acc2[m] = 0ull;
        for (int ch = 0; ch < 35; ch++) {
            ull w2 = pk2(Wa[ch * 128 + t], Wa[(35 + ch) * 128 + t]);
#pragma unroll
            for (int m = 0; m < 8; m++) {
                float e0 = semb[m][0][ch];
                acc2[m] = fma2(pk2(e0, e0), w2, acc2[m]);
            }
        }
#pragma unroll
        for (int m = 0; m < 8; m++) {
            float s, tt; upk2(acc2[m], s, tt);
            g_Psrc[(n0 + m) * 128 + t] = s;
            g_Ptgt[(n0 + m) * 128 + t] = tt;
        }
        int c = t & 63, r0 = t >> 6;
        ull v2[8];
#pragma unroll
        for (int m = 0; m < 8; m++) v2[m] = 0ull;
        for (int ch = 0; ch < 35; ch++) {
            float w = Wv[ch * 64 + c];
            ull wd = pk2(w, w);
#pragma unroll
            for (int m = 0; m < 8; m++)
                v2[m] = fma2(pk2(semb[m][r0][ch], semb[m][r0 + 2][ch]), wd, v2[m]);
        }
#pragma unroll
        for (int m = 0; m < 8; m++) {
            float a, b; upk2(v2[m], a, b);
            g_Vnode2[(n0 + m) * 128 + t] = make_float2(a, b);
        }
    } else {
        // ---------- rbf lerp table: one row/block; own .x and prev .y ----
        int dd = bid - (2048 + 1023 + 1024);      // 0..TB-1
        float dval = (float)dd * (24.0f / (float)TB);
        if (t < 16) {
            float x = (dval - (float)t * (20.0f / 15.0f)) * 0.8f;
            trig[t] = __expf(-x * x);
        }
        __syncthreads();
        float s = 0.f;
#pragma unroll
        for (int j = 0; j < 16; j++)
            s = fmaf(trig[j], Wa[(70 + j) * 128 + t], s);
        if (dd < TB - 1) g_rbfT2[dd * 128 + t].x = s;
        if (dd >= 1)     g_rbfT2[(dd - 1) * 128 + t].y = s;
    }
}

// ================= main kernel: one block per target node ===================
__global__ void __launch_bounds__(128)
k_main(const float* __restrict__ avec,
       const float* __restrict__ Wo,
       const float* __restrict__ Wg,
       const float* __restrict__ W2,
       float* __restrict__ out)
{
    __shared__ __align__(16) float4 s_meta[KK];       // {off, tblOff, frac, valid}
    __shared__ __align__(16) float s_lpart[KK][32];   // 4 partials x 8 heads
    __shared__ __align__(16) float s_aggT[64][4];     // transposed aggregate
    __shared__ __align__(16) float4 s_ep[4][32];      // epilogue partials
    __shared__ __align__(16) float4 s_ygT[32];        // gated y, transposed
    __shared__ float s_alphaT[8][32];                 // [head][edge]
    __shared__ float s_y0[32];

    int n = blockIdx.x, t = threadIdx.x;
    if (t < KK) {
        int s = g_knn[n * KK + t];
        float d = g_dist[n * KK + t];
        float valid = (isfinite(d) && d > 1e-3f) ? 1.f : 0.f;
        float u = fminf(d * TB_SCALE, (float)(TB - 2) + 0.999f);
        u = fmaxf(u, 0.f);
        int i = (int)u;
        s_meta[t] = make_float4(__int_as_float(s << 7),
                                __int_as_float(i << 7),
                                u - (float)i, valid);
    }
    float ptgt = g_Ptgt[n * 128 + t];
    float av = avec[t];                 // a_vec flat: t = h*16+k
    const float* psrcB = g_Psrc + t;
    const float* posAB = g_posA + (ptrdiff_t)(511 - n) * 128 + t;
    const float* rbfB  = reinterpret_cast<const float*>(g_rbfT2);
    __syncthreads();

    // ---- logits: one LDS.128 meta per edge; table-lerp rbf ----
#pragma unroll 3
    for (int e = 0; e < KK; e++) {
        float4 m = s_meta[e];
        int off  = __float_as_int(m.x);
        int toff = __float_as_int(m.y);
        float2 tv = *reinterpret_cast<const float2*>(rbfB + 2 * (toff + t));
        float acc = ptgt + psrcB[off] + posAB[off];
        acc = fmaf(m.z, tv.y - tv.x, acc + tv.x);
        float sig = __fdividef(1.f, 1.f + __expf(-acc));
        float p = acc * sig * av;                    // silu * a_vec
        p += __shfl_xor_sync(0xffffffffu, p, 8);
        p += __shfl_xor_sync(0xffffffffu, p, 4);
        if ((t & 15) < 4)
            s_lpart[e][(t >> 4) * 4 + (t & 3)] = p;
    }
    __syncthreads();

    // ---- softmax (warp 0: 4 lanes per head) ----
    if (t < 32) {
        int h = t >> 2, q = t & 3;
        float lg[8], vv[8];
        float mx = -1e30f;
        int cnt = 0;
        for (int e = q; e < KK; e += 4, cnt++) {
            float s = s_lpart[e][h * 4 + 0] + s_lpart[e][h * 4 + 1]
                    + s_lpart[e][h * 4 + 2] + s_lpart[e][h * 4 + 3];
            float valid = s_meta[e].w;
            float l = (s > 0.f) ? s : 0.2f * s;      // leaky_relu 0.2
            l = (valid > 0.f) ? l : -1e9f;
            lg[cnt] = l; vv[cnt] = valid;
            mx = fmaxf(mx, l);
        }
        mx = fmaxf(mx, __shfl_xor_sync(0xffffffffu, mx, 1));
        mx = fmaxf(mx, __shfl_xor_sync(0xffffffffu, mx, 2));
        float den = 0.f;
        cnt = 0;
        for (int e = q; e < KK; e += 4, cnt++) {
            float ex = __expf(lg[cnt] - mx) * vv[cnt];
            s_alphaT[h][e] = ex;
            den += ex;
        }
        den += __shfl_xor_sync(0xffffffffu, den, 1);
        den += __shfl_xor_sync(0xffffffffu, den, 2);
        float inv = __fdividef(1.f, den + 1e-9f);
        for (int e = q; e < KK; e += 4)
            s_alphaT[h][e] *= inv;
    }
    __syncthreads();

    // ---- value aggregation: interleaved float2 (rows rr, rr+2) ----
    {
        int cc = t & 63, rr = t >> 6;
        int h = cc >> 3;
        float a0 = 0.f, a1 = 0.f;
#pragma unroll 3
        for (int e = 0; e < KK; e++) {
            int off = __float_as_int(s_meta[e].x);
            float al = s_alphaT[h][e];
            float2 v = g_Vnode2[off + t];
            a0 = fmaf(al, v.x, a0);
            a1 = fmaf(al, v.y, a1);
        }
        s_aggT[cc][rr]     = a0;
        s_aggT[cc][rr + 2] = a1;
    }
    __syncthreads();

    // ---- epilogue: y = agg @ Wo (4 outputs/thread), gate, W2 ----
    int o = t & 31, s = t >> 5;
    const float4* aggT4 = reinterpret_cast<const float4*>(s_aggT);
    float4 acc4 = make_float4(0.f, 0.f, 0.f, 0.f);
#pragma unroll
    for (int i = 0; i < 16; i++) {
        int cc = s * 16 + i;
        float4 a4 = aggT4[cc];
        float w = Wo[cc * 32 + o];
        acc4.x = fmaf(a4.x, w, acc4.x);
        acc4.y = fmaf(a4.y, w, acc4.y);
        acc4.z = fmaf(a4.z, w, acc4.z);
        acc4.w = fmaf(a4.w, w, acc4.w);
    }
    s_ep[s][o] = acc4;
    __syncthreads();
    float4 y4;
    if (t < 32) {
        float4 p0 = s_ep[0][t], p1 = s_ep[1][t], p2 = s_ep[2][t], p3 = s_ep[3][t];
        y4.x = p0.x + p1.x + p2.x + p3.x;
        y4.y = p0.y + p1.y + p2.y + p3.y;
        y4.z = p0.z + p1.z + p2.z + p3.z;
        y4.w = p0.w + p1.w + p2.w + p3.w;
        s_y0[t] = y4.x;
    }
    __syncthreads();
    if (t < 32) {
        float g = 0.f;
#pragma unroll
        for (int j = 0; j < 32; j++) g = fmaf(s_y0[j], Wg[j * 32 + t], g);
        g = g * __fdividef(1.f, 1.f + __expf(-g));   // silu gate
        y4.x *= g; y4.y *= g; y4.z *= g; y4.w *= g;
        s_ygT[t] = y4;
    }
    __syncthreads();
    float4 acc2 = make_float4(0.f, 0.f, 0.f, 0.f);
#pragma unroll
    for (int i = 0; i < 8; i++) {
        int j = s * 8 + i;
        float4 a4 = s_ygT[j];
        float w = W2[j * 32 + o];
        acc2.x = fmaf(a4.x, w, acc2.x);
        acc2.y = fmaf(a4.y, w, acc2.y);
        acc2.z = fmaf(a4.z, w, acc2.z);
        acc2.w = fmaf(a4.w, w, acc2.w);
    }
    s_ep[s][o] = acc2;
    __syncthreads();
    if (t < 32) {
        float4 p0 = s_ep[0][t], p1 = s_ep[1][t], p2 = s_ep[2][t], p3 = s_ep[3][t];
        float* op = out + (size_t)n * 128;
        op[t]      = p0.x + p1.x + p2.x + p3.x;
        op[t + 32] = p0.y + p1.y + p2.y + p3.y;
        op[t + 64] = p0.z + p1.z + p2.z + p3.z;
        op[t + 96] = p0.w + p1.w + p2.w + p3.w;
    }
}

// ---------------- launch ----------------
extern "C" void kernel_launch(void* const* d_in, const int* in_sizes, int n_in,
                              void* d_out, int out_size)
{
    const float* rots     = (const float*)d_in[0];
    const float* trans    = (const float*)d_in[1];
    const float* node_emb = (const float*)d_in[2];
    const unsigned char* xm = (const unsigned char*)d_in[4];
    const unsigned char* nm = (const unsigned char*)d_in[5];
    const float* Wa = (const float*)d_in[6];
    const float* av = (const float*)d_in[7];
    const float* Wv = (const float*)d_in[8];
    const float* Wo = (const float*)d_in[9];
    const float* Wg = (const float*)d_in[10];
    const float* W2 = (const float*)d_in[11];
    float* out = (float*)d_out;

    k_prep<<<2048 + 1023 + 1024 + TB, 128>>>(trans, rots, node_emb, xm, nm, Wa, Wv);
    k_main<<<NN, 128>>>(av, Wo, Wg, W2, out);
}

// round 12
// speedup vs baseline: 2.3073x; 1.0188x over previous
#include <cuda_runtime.h>
#include <math.h>
#include <stddef.h>

#define NN 8192
#define LL 512
#define KK 30
#define TB 1024                 // rbf table bins over [0,24)
#define TB_SCALE (1024.0f / 24.0f)

typedef unsigned long long ull;

// ---------------- packed f32x2 helpers (used in prep only) ----------------
__device__ __forceinline__ ull pk2(float a, float b) {
    ull r; asm("mov.b64 %0, {%1,%2};" : "=l"(r) : "f"(a), "f"(b)); return r;
}
__device__ __forceinline__ void upk2(ull v, float& a, float& b) {
    asm("mov.b64 {%0,%1}, %2;" : "=f"(a), "=f"(b) : "l"(v));
}
__device__ __forceinline__ ull fma2(ull x, ull y, ull a) {
    ull r; asm("fma.rn.f32x2 %0, %1, %2, %3;" : "=l"(r) : "l"(x), "l"(y), "l"(a));
    return r;
}

// ---------------- device scratch ----------------
__device__ int    g_knn [NN * KK];
__device__ float  g_dist[NN * KK];
__device__ float  g_Psrc[NN * 128];
__device__ float  g_Ptgt[NN * 128];
__device__ float2 g_Vnode2[NN * 128];  // {rows (r, r+2)} interleaved
__device__ float  g_posA[1023 * 128];
__device__ float2 g_rbfT2[TB * 128];   // {T[dd][c], T[dd+1][c]-T[dd][c]}

// ============ merged prep: knn | posA | node | rbf-table by blockIdx ========
__global__ void k_prep(const float* __restrict__ trans,
                       const float* __restrict__ rots,
                       const float* __restrict__ node_emb,
                       const unsigned char* __restrict__ xm,
                       const unsigned char* __restrict__ nm,
                       const float* __restrict__ Wa,
                       const float* __restrict__ Wv)
{
    __shared__ __align__(16) char u_smem[11520];  // pos(6144) / spill(11520) / semb(4608)
    __shared__ float trig[32];
    __shared__ int   s_u8;
    int bid = blockIdx.x, t = threadIdx.x;

    if (bid < 2048) {
        // ---------- kNN: 4 targets/block, warp each; sort + redux extract ----
        float* sx = (float*)u_smem;           // [512]
        float* sy = sx + LL;
        float* sz = sy + LL;
        int g0 = bid * 4;
        int base = (g0 >> 9) << 9;
        for (int i = t; i < LL; i += 128) {
            const float* p = trans + (size_t)(base + i) * 3;
            sx[i] = p[0]; sy[i] = p[1]; sz[i] = p[2];
        }
        __syncthreads();
        int warp = t >> 5, lane = t & 31;
        int tgt = g0 + warp;
        int tl = tgt & 511;
        float px = sx[tl], py = sy[tl], pz = sz[tl];

        unsigned key[16]; int idx[16];
#pragma unroll
        for (int q = 0; q < 16; q++) {
            int c = lane + (q << 5);
            float dx = sx[c] - px, dy = sy[c] - py, dz = sz[c] - pz;
            float d2 = dx * dx + dy * dy + dz * dz;
            if (c == tl) d2 = 1e30f;
            key[q] = __float_as_uint(d2);
            idx[q] = c;
        }
        __syncthreads();   // all warps done reading positions before spill
        // Batcher odd-even mergesort, ascending by (key, idx)
#pragma unroll
        for (int p = 1; p < 16; p <<= 1) {
#pragma unroll
            for (int k = p; k >= 1; k >>= 1) {
#pragma unroll
                for (int j = k % p; j + k < 16; j += 2 * k) {
#pragma unroll
                    for (int i = 0; i < k; i++) {
                        int a = i + j, b = i + j + k;
                        if (b < 16 && (a / (2 * p)) == (b / (2 * p))) {
                            bool sw = (key[a] > key[b]) ||
                                      (key[a] == key[b] && idx[a] > idx[b]);
                            unsigned ka = sw ? key[b] : key[a];
                            unsigned kb = sw ? key[a] : key[b];
                            int ia = sw ? idx[b] : idx[a];
                            int ib = sw ? idx[a] : idx[b];
                            key[a] = ka; key[b] = kb; idx[a] = ia; idx[b] = ib;
                        }
                    }
                }
            }
        }
        unsigned* skey = (unsigned*)u_smem;                       // [4*15*32]
        unsigned short* sidx = (unsigned short*)(u_smem + 7680);  // [4*15*32]
        int lb = warp * 480 + lane;
#pragma unroll
        for (int q = 1; q < 16; q++) {
            skey[lb + (q - 1) * 32] = key[q];
            sidx[lb + (q - 1) * 32] = (unsigned short)idx[q];
        }
        unsigned ck = key[0]; int ci = idx[0];
        int ptr = 0;
        for (int it = 0; it < KK; it++) {
            unsigned mv = __reduce_min_sync(0xffffffffu, ck);
            unsigned ti = (ck == mv) ? (unsigned)ci : 0xffffffffu;
            unsigned mi = __reduce_min_sync(0xffffffffu, ti);
            if (lane == 0) {
                g_knn [tgt * KK + it] = base + (int)mi;
                g_dist[tgt * KK + it] = sqrtf(__uint_as_float(mv));
            }
            if (ck == mv && (unsigned)ci == mi) {
                if (ptr < 15) {
                    ck = skey[lb + ptr * 32];
                    ci = (int)sidx[lb + ptr * 32];
                    ptr++;
                } else ck = 0xffffffffu;
            }
        }
    } else if (bid < 2048 + 1023) {
        // ---------- posA table ----------
        int dd = bid - 2048;
        float delta = (float)(dd - 511);
        if (t < 8) {
            float freq = expf(-(float)(2 * t) * (9.210340371976184f / 16.0f));
            float ang = delta * freq;
            trig[t]     = cosf(ang);
            trig[8 + t] = sinf(ang);
        }
        __syncthreads();
        float s = 0.f;
#pragma unroll
        for (int j = 0; j < 8; j++) {
            s = fmaf(trig[j],     Wa[(86 + j) * 128 + t], s);
            s = fmaf(trig[8 + j], Wa[(94 + j) * 128 + t], s);
        }
        g_posA[dd * 128 + t] = s;
    } else if (bid < 2048 + 1023 + 1024) {
        // ---------- node precompute: 8 nodes / block ----------
        float (*semb)[4][36] = (float (*)[4][36])u_smem;
        int n0 = (bid - (2048 + 1023)) * 8;
        if (t < 64) {
            int any = 0;
#pragma unroll
            for (int j = 1; j < 4; j++) any |= (int)xm[4 * t + j];
            unsigned b = __ballot_sync(0xffffffffu, any != 0);
            if (t == 0) s_u8 = (b != 0u) ? 1 : 0;
        }
        __syncthreads();
        int u8 = s_u8;
        for (int m = 0; m < 8; m++) {
            int n = n0 + m;
            int r = t >> 5, c = t & 31;
            semb[m][r][c] = node_emb[n * 128 + t];
            if (t == 0) {
                const float* R = rots + n * 9;
                const float bx0 = -0.525f, by0 = 1.363f, bx2 = 1.526f;
#pragma unroll
                for (int i = 0; i < 3; i++) {
                    float r0 = R[i * 3 + 0], r1 = R[i * 3 + 1];
                    semb[m][1 + i][32 + 0] = r0 * bx0 + r1 * by0;
                    semb[m][1 + i][32 + 1] = 0.f;
                    semb[m][1 + i][32 + 2] = r0 * bx2;
                }
                int xv = u8 ? (int)xm[n] : (int)xm[n * 4];
                int nv = u8 ? (int)nm[n] : (int)nm[n * 4];
                semb[m][0][32] = 0.f;
                semb[m][0][33] = 0.f;
                semb[m][0][34] = (nv && !xv) ? 1.f : 0.f;
            }
        }
        __syncthreads();
        ull acc2[8];
#pragma unroll
        for (int m = 0; m < 8; m++) acc2[m] = 0ull;
        for (int ch = 0; ch < 35; ch++) {
            ull w2 = pk2(Wa[ch * 128 + t], Wa[(35 + ch) * 128 + t]);
#pragma unroll
            for (int m = 0; m < 8; m++) {
                float e0 = semb[m][0][ch];
                acc2[m] = fma2(pk2(e0, e0), w2, acc2[m]);
            }
        }
#pragma unroll
        for (int m = 0; m < 8; m++) {
            float s, tt; upk2(acc2[m], s, tt);
            g_Psrc[(n0 + m) * 128 + t] = s;
            g_Ptgt[(n0 + m) * 128 + t] = tt;
        }
        int c = t & 63, r0 = t >> 6;
        ull v2[8];
#pragma unroll
        for (int m = 0; m < 8; m++) v2[m] = 0ull;
        for (int ch = 0; ch < 35; ch++) {
            float w = Wv[ch * 64 + c];
            ull wd = pk2(w, w);
#pragma unroll
            for (int m = 0; m < 8; m++)
                v2[m] = fma2(pk2(semb[m][r0][ch], semb[m][r0 + 2][ch]), wd, v2[m]);
        }
#pragma unroll
        for (int m = 0; m < 8; m++) {
            float a, b; upk2(v2[m], a, b);
            g_Vnode2[(n0 + m) * 128 + t] = make_float2(a, b);
        }
    } else {
        // ---------- rbf lerp table: row dd -> {T(dd), T(dd+1)-T(dd)} ----------
        int dd = bid - (2048 + 1023 + 1024);      // 0..TB-1
        if (t < 32) {
            int j = t & 15;
            float dval = (float)(dd + (t >> 4)) * (24.0f / (float)TB);
            float x = (dval - (float)j * (20.0f / 15.0f)) * 0.8f;
            trig[t] = __expf(-x * x);
        }
        __syncthreads();
        float s0 = 0.f, s1 = 0.f;
#pragma unroll
        for (int j = 0; j < 16; j++) {
            float w = Wa[(70 + j) * 128 + t];
            s0 = fmaf(trig[j],      w, s0);
            s1 = fmaf(trig[16 + j], w, s1);
        }
        g_rbfT2[dd * 128 + t] = make_float2(s0, s1 - s0);
    }
}

// ================= main kernel: one block per target node ===================
__global__ void __launch_bounds__(128)
k_main(const float* __restrict__ avec,
       const float* __restrict__ Wo,
       const float* __restrict__ Wg,
       const float* __restrict__ W2,
       float* __restrict__ out)
{
    __shared__ __align__(16) float4 s_meta[KK];       // {off, tblOff, frac, valid}
    __shared__ __align__(16) float s_lpart[KK][64];   // 8 partials x 8 heads
    __shared__ __align__(16) float s_aggT[64][4];     // transposed aggregate
    __shared__ __align__(16) float4 s_ep[4][32];      // epilogue partials
    __shared__ __align__(16) float4 s_ygT[32];        // gated y, transposed
    __shared__ float s_alphaT[8][32];                 // [head][edge]
    __shared__ float s_y0[32];

    int n = blockIdx.x, t = threadIdx.x;
    if (t < KK) {
        int s = g_knn[n * KK + t];
        float d = g_dist[n * KK + t];
        float valid = (isfinite(d) && d > 1e-3f) ? 1.f : 0.f;
        float u = fminf(d * TB_SCALE, (float)(TB - 2) + 0.999f);
        u = fmaxf(u, 0.f);
        int i = (int)u;
        s_meta[t] = make_float4(__int_as_float(s << 7),
                                __int_as_float(i << 7),
                                u - (float)i, valid);
    }
    float ptgt = g_Ptgt[n * 128 + t];
    float av = avec[t];                 // a_vec flat: t = h*16+k
    const float* psrcB = g_Psrc + t;
    const float* posAB = g_posA + (ptrdiff_t)(511 - n) * 128 + t;
    __syncthreads();

    // ---- logits: one LDS.128 meta per edge; {T,dT} lerp; ONE shfl ----
#pragma unroll 3
    for (int e = 0; e < KK; e++) {
        float4 m = s_meta[e];
        int off  = __float_as_int(m.x);
        int toff = __float_as_int(m.y);
        float2 tv = g_rbfT2[toff + t];
        float acc = ptgt + psrcB[off] + posAB[off];
        acc = acc + fmaf(m.z, tv.y, tv.x);
        float sig = __fdividef(1.f, 1.f + __expf(-acc));
        float p = acc * sig * av;                    // silu * a_vec
        p += __shfl_xor_sync(0xffffffffu, p, 8);
        if ((t & 15) < 8)
            s_lpart[e][(t >> 4) * 8 + (t & 7)] = p;  // head*8 + k
    }
    __syncthreads();

    // ---- softmax (warp 0: 4 lanes per head; full 8-partial sum per lane) ----
    if (t < 32) {
        int h = t >> 2, q = t & 3;
        float lg[8], vv[8];
        float mx = -1e30f;
        int cnt = 0;
        for (int e = q; e < KK; e += 4, cnt++) {
            float4 pa = *reinterpret_cast<const float4*>(&s_lpart[e][h * 8]);
            float4 pb = *reinterpret_cast<const float4*>(&s_lpart[e][h * 8 + 4]);
            float s = (pa.x + pa.y) + (pa.z + pa.w)
                    + (pb.x + pb.y) + (pb.z + pb.w);
            float valid = s_meta[e].w;
            float l = (s > 0.f) ? s : 0.2f * s;      // leaky_relu 0.2
            l = (valid > 0.f) ? l : -1e9f;
            lg[cnt] = l; vv[cnt] = valid;
            mx = fmaxf(mx, l);
        }
        mx = fmaxf(mx, __shfl_xor_sync(0xffffffffu, mx, 1));
        mx = fmaxf(mx, __shfl_xor_sync(0xffffffffu, mx, 2));
        float den = 0.f;
        cnt = 0;
        for (int e = q; e < KK; e += 4, cnt++) {
            float ex = __expf(lg[cnt] - mx) * vv[cnt];
            s_alphaT[h][e] = ex;
            den += ex;
        }
        den += __shfl_xor_sync(0xffffffffu, den, 1);
        den += __shfl_xor_sync(0xffffffffu, den, 2);
        float inv = __fdividef(1.f, den + 1e-9f);
        for (int e = q; e < KK; e += 4)
            s_alphaT[h][e] *= inv;
    }
    __syncthreads();

    // ---- value aggregation: interleaved float2 (rows rr, rr+2) ----
    {
        int cc = t & 63, rr = t >> 6;
        int h = cc >> 3;
        float a0 = 0.f, a1 = 0.f;
#pragma unroll 3
        for (int e = 0; e < KK; e++) {
            int off = __float_as_int(s_meta[e].x);
            float al = s_alphaT[h][e];
            float2 v = g_Vnode2[off + t];
            a0 = fmaf(al, v.x, a0);
            a1 = fmaf(al, v.y, a1);
        }
        s_aggT[cc][rr]     = a0;
        s_aggT[cc][rr + 2] = a1;
    }
    __syncthreads();

    // ---- epilogue: y = agg @ Wo (4 outputs/thread), gate, W2 ----
    int o = t & 31, s = t >> 5;
    const float4* aggT4 = reinterpret_cast<const float4*>(s_aggT);
    float4 acc4 = make_float4(0.f, 0.f, 0.f, 0.f);
#pragma unroll
    for (int i = 0; i < 16; i++) {
        int cc = s * 16 + i;
        float4 a4 = aggT4[cc];
        float w = Wo[cc * 32 + o];
        acc4.x = fmaf(a4.x, w, acc4.x);
        acc4.y = fmaf(a4.y, w, acc4.y);
        acc4.z = fmaf(a4.z, w, acc4.z);
        acc4.w = fmaf(a4.w, w, acc4.w);
    }
    s_ep[s][o] = acc4;
    __syncthreads();
    float4 y4;
    if (t < 32) {
        float4 p0 = s_ep[0][t], p1 = s_ep[1][t], p2 = s_ep[2][t], p3 = s_ep[3][t];
        y4.x = p0.x + p1.x + p2.x + p3.x;
        y4.y = p0.y + p1.y + p2.y + p3.y;
        y4.z = p0.z + p1.z + p2.z + p3.z;
        y4.w = p0.w + p1.w + p2.w + p3.w;
        s_y0[t] = y4.x;
    }
    __syncthreads();
    if (t < 32) {
        float g = 0.f;
#pragma unroll
        for (int j = 0; j < 32; j++) g = fmaf(s_y0[j], Wg[j * 32 + t], g);
        g = g * __fdividef(1.f, 1.f + __expf(-g));   // silu gate
        y4.x *= g; y4.y *= g; y4.z *= g; y4.w *= g;
        s_ygT[t] = y4;
    }
    __syncthreads();
    float4 acc2 = make_float4(0.f, 0.f, 0.f, 0.f);
#pragma unroll
    for (int i = 0; i < 8; i++) {
        int j = s * 8 + i;
        float4 a4 = s_ygT[j];
        float w = W2[j * 32 + o];
        acc2.x = fmaf(a4.x, w, acc2.x);
        acc2.y = fmaf(a4.y, w, acc2.y);
        acc2.z = fmaf(a4.z, w, acc2.z);
        acc2.w = fmaf(a4.w, w, acc2.w);
    }
    s_ep[s][o] = acc2;
    __syncthreads();
    if (t < 32) {
        float4 p0 = s_ep[0][t], p1 = s_ep[1][t], p2 = s_ep[2][t], p3 = s_ep[3][t];
        float* op = out + (size_t)n * 128;
        op[t]      = p0.x + p1.x + p2.x + p3.x;
        op[t + 32] = p0.y + p1.y + p2.y + p3.y;
        op[t + 64] = p0.z + p1.z + p2.z + p3.z;
        op[t + 96] = p0.w + p1.w + p2.w + p3.w;
    }
}

// ---------------- launch ----------------
extern "C" void kernel_launch(void* const* d_in, const int* in_sizes, int n_in,
                              void* d_out, int out_size)
{
    const float* rots     = (const float*)d_in[0];
    const float* trans    = (const float*)d_in[1];
    const float* node_emb = (const float*)d_in[2];
    const unsigned char* xm = (const unsigned char*)d_in[4];
    const unsigned char* nm = (const unsigned char*)d_in[5];
    const float* Wa = (const float*)d_in[6];
    const float* av = (const float*)d_in[7];
    const float* Wv = (const float*)d_in[8];
    const float* Wo = (const float*)d_in[9];
    const float* Wg = (const float*)d_in[10];
    const float* W2 = (const float*)d_in[11];
    float* out = (float*)d_out;

    k_prep<<<2048 + 1023 + 1024 + TB, 128>>>(trans, rots, node_emb, xm, nm, Wa, Wv);
    k_main<<<NN, 128>>>(av, Wo, Wg, W2, out);
}

// round 13
// speedup vs baseline: 2.5530x; 1.1065x over previous
#include <cuda_runtime.h>
#include <math.h>
#include <stddef.h>

#define NN 8192
#define LL 512
#define KK 30
#define TB 1024                 // rbf table bins over [0,24)
#define TB_SCALE (1024.0f / 24.0f)

typedef unsigned long long ull;

// ---------------- packed f32x2 helpers (used in prep only) ----------------
__device__ __forceinline__ ull pk2(float a, float b) {
    ull r; asm("mov.b64 %0, {%1,%2};" : "=l"(r) : "f"(a), "f"(b)); return r;
}
__device__ __forceinline__ void upk2(ull v, float& a, float& b) {
    asm("mov.b64 {%0,%1}, %2;" : "=f"(a), "=f"(b) : "l"(v));
}
__device__ __forceinline__ ull fma2(ull x, ull y, ull a) {
    ull r; asm("fma.rn.f32x2 %0, %1, %2, %3;" : "=l"(r) : "l"(x), "l"(y), "l"(a));
    return r;
}

// ---------------- device scratch ----------------
__device__ int    g_knn [NN * KK];
__device__ float  g_dist[NN * KK];
__device__ float  g_Psrc[NN * 128];
__device__ float  g_Ptgt[NN * 128];
__device__ float2 g_Vnode2[NN * 128];  // elem i: {row (i>>6), ch (i&63)} pair rows r,r+2
__device__ float  g_posA[1023 * 128];
__device__ float2 g_rbfT2[TB * 128];   // {T[dd][c], T[dd+1][c]-T[dd][c]}

// ============ merged prep: knn | posA | node | rbf-table by blockIdx ========
__global__ void k_prep(const float* __restrict__ trans,
                       const float* __restrict__ rots,
                       const float* __restrict__ node_emb,
                       const unsigned char* __restrict__ xm,
                       const unsigned char* __restrict__ nm,
                       const float* __restrict__ Wa,
                       const float* __restrict__ Wv)
{
    __shared__ __align__(16) char u_smem[11520];  // pos(6144) / spill(11520) / semb(4608)
    __shared__ float trig[32];
    __shared__ int   s_u8;
    int bid = blockIdx.x, t = threadIdx.x;

    if (bid < 2048) {
        // ---------- kNN: 4 targets/block, warp each; sort + redux extract ----
        float* sx = (float*)u_smem;           // [512]
        float* sy = sx + LL;
        float* sz = sy + LL;
        int g0 = bid * 4;
        int base = (g0 >> 9) << 9;
        for (int i = t; i < LL; i += 128) {
            const float* p = trans + (size_t)(base + i) * 3;
            sx[i] = p[0]; sy[i] = p[1]; sz[i] = p[2];
        }
        __syncthreads();
        int warp = t >> 5, lane = t & 31;
        int tgt = g0 + warp;
        int tl = tgt & 511;
        float px = sx[tl], py = sy[tl], pz = sz[tl];

        unsigned key[16]; int idx[16];
#pragma unroll
        for (int q = 0; q < 16; q++) {
            int c = lane + (q << 5);
            float dx = sx[c] - px, dy = sy[c] - py, dz = sz[c] - pz;
            float d2 = dx * dx + dy * dy + dz * dz;
            if (c == tl) d2 = 1e30f;
            key[q] = __float_as_uint(d2);
            idx[q] = c;
        }
        __syncthreads();   // all warps done reading positions before spill
        // Batcher odd-even mergesort, ascending by (key, idx)
#pragma unroll
        for (int p = 1; p < 16; p <<= 1) {
#pragma unroll
            for (int k = p; k >= 1; k >>= 1) {
#pragma unroll
                for (int j = k % p; j + k < 16; j += 2 * k) {
#pragma unroll
                    for (int i = 0; i < k; i++) {
                        int a = i + j, b = i + j + k;
                        if (b < 16 && (a / (2 * p)) == (b / (2 * p))) {
                            bool sw = (key[a] > key[b]) ||
                                      (key[a] == key[b] && idx[a] > idx[b]);
                            unsigned ka = sw ? key[b] : key[a];
                            unsigned kb = sw ? key[a] : key[b];
                            int ia = sw ? idx[b] : idx[a];
                            int ib = sw ? idx[a] : idx[b];
                            key[a] = ka; key[b] = kb; idx[a] = ia; idx[b] = ib;
                        }
                    }
                }
            }
        }
        unsigned* skey = (unsigned*)u_smem;                       // [4*15*32]
        unsigned short* sidx = (unsigned short*)(u_smem + 7680);  // [4*15*32]
        int lb = warp * 480 + lane;
#pragma unroll
        for (int q = 1; q < 16; q++) {
            skey[lb + (q - 1) * 32] = key[q];
            sidx[lb + (q - 1) * 32] = (unsigned short)idx[q];
        }
        unsigned ck = key[0]; int ci = idx[0];
        int ptr = 0;
        for (int it = 0; it < KK; it++) {
            unsigned mv = __reduce_min_sync(0xffffffffu, ck);
            unsigned ti = (ck == mv) ? (unsigned)ci : 0xffffffffu;
            unsigned mi = __reduce_min_sync(0xffffffffu, ti);
            if (lane == 0) {
                g_knn [tgt * KK + it] = base + (int)mi;
                g_dist[tgt * KK + it] = sqrtf(__uint_as_float(mv));
            }
            if (ck == mv && (unsigned)ci == mi) {
                if (ptr < 15) {
                    ck = skey[lb + ptr * 32];
                    ci = (int)sidx[lb + ptr * 32];
                    ptr++;
                } else ck = 0xffffffffu;
            }
        }
    } else if (bid < 2048 + 1023) {
        // ---------- posA table ----------
        int dd = bid - 2048;
        float delta = (float)(dd - 511);
        if (t < 8) {
            float freq = expf(-(float)(2 * t) * (9.210340371976184f / 16.0f));
            float ang = delta * freq;
            trig[t]     = cosf(ang);
            trig[8 + t] = sinf(ang);
        }
        __syncthreads();
        float s = 0.f;
#pragma unroll
        for (int j = 0; j < 8; j++) {
            s = fmaf(trig[j],     Wa[(86 + j) * 128 + t], s);
            s = fmaf(trig[8 + j], Wa[(94 + j) * 128 + t], s);
        }
        g_posA[dd * 128 + t] = s;
    } else if (bid < 2048 + 1023 + 1024) {
        // ---------- node precompute: 8 nodes / block ----------
        float (*semb)[4][36] = (float (*)[4][36])u_smem;
        int n0 = (bid - (2048 + 1023)) * 8;
        if (t < 64) {
            int any = 0;
#pragma unroll
            for (int j = 1; j < 4; j++) any |= (int)xm[4 * t + j];
            unsigned b = __ballot_sync(0xffffffffu, any != 0);
            if (t == 0) s_u8 = (b != 0u) ? 1 : 0;
        }
        __syncthreads();
        int u8 = s_u8;
        for (int m = 0; m < 8; m++) {
            int n = n0 + m;
            int r = t >> 5, c = t & 31;
            semb[m][r][c] = node_emb[n * 128 + t];
            if (t == 0) {
                const float* R = rots + n * 9;
                const float bx0 = -0.525f, by0 = 1.363f, bx2 = 1.526f;
#pragma unroll
                for (int i = 0; i < 3; i++) {
                    float r0 = R[i * 3 + 0], r1 = R[i * 3 + 1];
                    semb[m][1 + i][32 + 0] = r0 * bx0 + r1 * by0;
                    semb[m][1 + i][32 + 1] = 0.f;
                    semb[m][1 + i][32 + 2] = r0 * bx2;
                }
                int xv = u8 ? (int)xm[n] : (int)xm[n * 4];
                int nv = u8 ? (int)nm[n] : (int)nm[n * 4];
                semb[m][0][32] = 0.f;
                semb[m][0][33] = 0.f;
                semb[m][0][34] = (nv && !xv) ? 1.f : 0.f;
            }
        }
        __syncthreads();
        ull acc2[8];
#pragma unroll
        for (int m = 0; m < 8; m++) acc2[m] = 0ull;
        for (int ch = 0; ch < 35; ch++) {
            ull w2 = pk2(Wa[ch * 128 + t], Wa[(35 + ch) * 128 + t]);
#pragma unroll
            for (int m = 0; m < 8; m++) {
                float e0 = semb[m][0][ch];
                acc2[m] = fma2(pk2(e0, e0), w2, acc2[m]);
            }
        }
#pragma unroll
        for (int m = 0; m < 8; m++) {
            float s, tt; upk2(acc2[m], s, tt);
            g_Psrc[(n0 + m) * 128 + t] = s;
            g_Ptgt[(n0 + m) * 128 + t] = tt;
        }
        int c = t & 63, r0 = t >> 6;
        ull v2[8];
#pragma unroll
        for (int m = 0; m < 8; m++) v2[m] = 0ull;
        for (int ch = 0; ch < 35; ch++) {
            float w = Wv[ch * 64 + c];
            ull wd = pk2(w, w);
#pragma unroll
            for (int m = 0; m < 8; m++)
                v2[m] = fma2(pk2(semb[m][r0][ch], semb[m][r0 + 2][ch]), wd, v2[m]);
        }
#pragma unroll
        for (int m = 0; m < 8; m++) {
            float a, b; upk2(v2[m], a, b);
            g_Vnode2[(n0 + m) * 128 + t] = make_float2(a, b);
        }
    } else {
        // ---------- rbf lerp table: row dd -> {T(dd), T(dd+1)-T(dd)} ----------
        int dd = bid - (2048 + 1023 + 1024);      // 0..TB-1
        if (t < 32) {
            int j = t & 15;
            float dval = (float)(dd + (t >> 4)) * (24.0f / (float)TB);
            float x = (dval - (float)j * (20.0f / 15.0f)) * 0.8f;
            trig[t] = __expf(-x * x);
        }
        __syncthreads();
        float s0 = 0.f, s1 = 0.f;
#pragma unroll
        for (int j = 0; j < 16; j++) {
            float w = Wa[(70 + j) * 128 + t];
            s0 = fmaf(trig[j],      w, s0);
            s1 = fmaf(trig[16 + j], w, s1);
        }
        g_rbfT2[dd * 128 + t] = make_float2(s0, s1 - s0);
    }
}

// ================= main kernel: one block per target node ===================
// channel-pair layout: group g = t>>6 handles edges 2*it+g; lane-in-group
// c = t&63 owns channels (2c, 2c+1).
__global__ void __launch_bounds__(128)
k_main(const float* __restrict__ avec,
       const float* __restrict__ Wo,
       const float* __restrict__ Wg,
       const float* __restrict__ W2,
       float* __restrict__ out)
{
    __shared__ __align__(16) float4 s_meta[KK];       // {off64, toff64, frac, valid}
    __shared__ float s_logit[KK][8];                  // final per-head logits
    __shared__ float s_alphaT[8][32];                 // [head][edge]
    __shared__ __align__(16) float4 s_vp[2][64];      // value partials per group
    __shared__ __align__(16) float s_aggT[64][4];     // transposed aggregate
    __shared__ __align__(16) float4 s_ep[4][32];      // epilogue partials
    __shared__ __align__(16) float4 s_ygT[32];        // gated y, transposed
    __shared__ float s_y0[32];

    int n = blockIdx.x, t = threadIdx.x;
    int g = t >> 6, c = t & 63;

    if (t < KK) {
        int s = g_knn[n * KK + t];
        float d = g_dist[n * KK + t];
        float valid = (isfinite(d) && d > 1e-3f) ? 1.f : 0.f;
        float u = fminf(d * TB_SCALE, (float)(TB - 2) + 0.999f);
        u = fmaxf(u, 0.f);
        int i = (int)u;
        s_meta[t] = make_float4(__int_as_float(s << 6),     // src*64
                                __int_as_float(i << 6),     // tidx*64
                                u - (float)i, valid);
    }
    float2 ptgt2 = reinterpret_cast<const float2*>(g_Ptgt)[n * 64 + c];
    float2 av2   = reinterpret_cast<const float2*>(avec)[c];
    const float2* psrc2 = reinterpret_cast<const float2*>(g_Psrc);
    const float2* posA2 = reinterpret_cast<const float2*>(g_posA)
                          + (ptrdiff_t)(511 - n) * 64;
    const float4* rbf4  = reinterpret_cast<const float4*>(g_rbfT2);
    const float4* vno4  = reinterpret_cast<const float4*>(g_Vnode2);
    __syncthreads();

    // ---- logits: 2 edges in parallel (one per 64-thread group) ----
#pragma unroll 3
    for (int it = 0; it < KK / 2; it++) {
        int e = 2 * it + g;
        float4 m = s_meta[e];
        int off  = __float_as_int(m.x);
        int toff = __float_as_int(m.y);
        float2 ps = psrc2[off + c];
        float2 pa = posA2[off + c];
        float4 tv = rbf4[toff + c];       // {T0, dT0, T1, dT1}
        float a0 = ptgt2.x + ps.x + pa.x + fmaf(m.z, tv.y, tv.x);
        float a1 = ptgt2.y + ps.y + pa.y + fmaf(m.z, tv.w, tv.z);
        float h0 = a0 * __fdividef(1.f, 1.f + __expf(-a0));   // silu
        float h1 = a1 * __fdividef(1.f, 1.f + __expf(-a1));
        float p = h0 * av2.x + h1 * av2.y;
        p += __shfl_xor_sync(0xffffffffu, p, 1);
        p += __shfl_xor_sync(0xffffffffu, p, 2);
        p += __shfl_xor_sync(0xffffffffu, p, 4);
        if ((c & 7) == 0)
            s_logit[e][c >> 3] = p;       // full 16-channel head sum
    }
    __syncthreads();

    // ---- softmax (warp 0: 4 lanes per head) ----
    if (t < 32) {
        int h = t >> 2, q = t & 3;
        float lg[8], vv[8];
        float mx = -1e30f;
        int cnt = 0;
        for (int e = q; e < KK; e += 4, cnt++) {
            float s = s_logit[e][h];
            float valid = s_meta[e].w;
            float l = (s > 0.f) ? s : 0.2f * s;      // leaky_relu 0.2
            l = (valid > 0.f) ? l : -1e9f;
            lg[cnt] = l; vv[cnt] = valid;
            mx = fmaxf(mx, l);
        }
        mx = fmaxf(mx, __shfl_xor_sync(0xffffffffu, mx, 1));
        mx = fmaxf(mx, __shfl_xor_sync(0xffffffffu, mx, 2));
        float den = 0.f;
        cnt = 0;
        for (int e = q; e < KK; e += 4, cnt++) {
            float ex = __expf(lg[cnt] - mx) * vv[cnt];
            s_alphaT[h][e] = ex;
            den += ex;
        }
        den += __shfl_xor_sync(0xffffffffu, den, 1);
        den += __shfl_xor_sync(0xffffffffu, den, 2);
        float inv = __fdividef(1.f, den + 1e-9f);
        for (int e = q; e < KK; e += 4)
            s_alphaT[h][e] *= inv;
    }
    __syncthreads();

    // ---- value aggregation: 2 edges in parallel, float4 Vnode loads ----
    {
        // float4 j covers Vnode2 elements 2j,2j+1: {r,c0},{r+2,c0},{r,c0+1},{r+2,c0+1}
        int c0 = (2 * c) & 63;
        int h = c0 >> 3;
        float4 acc = make_float4(0.f, 0.f, 0.f, 0.f);
#pragma unroll 3
        for (int it = 0; it < KK / 2; it++) {
            int e = 2 * it + g;
            int off = __float_as_int(s_meta[e].x);   // src*64
            float al = s_alphaT[h][e];
            float4 v = vno4[off + c];
            acc.x = fmaf(al, v.x, acc.x);
            acc.y = fmaf(al, v.y, acc.y);
            acc.z = fmaf(al, v.z, acc.z);
            acc.w = fmaf(al, v.w, acc.w);
        }
        s_vp[g][c] = acc;
    }
    __syncthreads();
    if (t < 64) {
        float4 p0 = s_vp[0][t], p1 = s_vp[1][t];
        int c0 = (2 * t) & 63;
        int r  = (2 * t) >> 6;                       // 0 or 1
        s_aggT[c0][r]         = p0.x + p1.x;
        s_aggT[c0][r + 2]     = p0.y + p1.y;
        s_aggT[c0 + 1][r]     = p0.z + p1.z;
        s_aggT[c0 + 1][r + 2] = p0.w + p1.w;
    }
    __syncthreads();

    // ---- epilogue: y = agg @ Wo (4 outputs/thread), gate, W2 ----
    int o = t & 31, s = t >> 5;
    const float4* aggT4 = reinterpret_cast<const float4*>(s_aggT);
    float4 acc4 = make_float4(0.f, 0.f, 0.f, 0.f);
#pragma unroll
    for (int i = 0; i < 16; i++) {
        int cc = s * 16 + i;
        float4 a4 = aggT4[cc];
        float w = Wo[cc * 32 + o];
        acc4.x = fmaf(a4.x, w, acc4.x);
        acc4.y = fmaf(a4.y, w, acc4.y);
        acc4.z = fmaf(a4.z, w, acc4.z);
        acc4.w = fmaf(a4.w, w, acc4.w);
    }
    s_ep[s][o] = acc4;
    __syncthreads();
    float4 y4;
    if (t < 32) {
        float4 p0 = s_ep[0][t], p1 = s_ep[1][t], p2 = s_ep[2][t], p3 = s_ep[3][t];
        y4.x = p0.x + p1.x + p2.x + p3.x;
        y4.y = p0.y + p1.y + p2.y + p3.y;
        y4.z = p0.z + p1.z + p2.z + p3.z;
        y4.w = p0.w + p1.w + p2.w + p3.w;
        s_y0[t] = y4.x;
    }
    __syncthreads();
    if (t < 32) {
        float gg = 0.f;
#pragma unroll
        for (int j = 0; j < 32; j++) gg = fmaf(s_y0[j], Wg[j * 32 + t], gg);
        gg = gg * __fdividef(1.f, 1.f + __expf(-gg));  // silu gate
        y4.x *= gg; y4.y *= gg; y4.z *= gg; y4.w *= gg;
        s_ygT[t] = y4;
    }
    __syncthreads();
    float4 acc2 = make_float4(0.f, 0.f, 0.f, 0.f);
#pragma unroll
    for (int i = 0; i < 8; i++) {
        int j = s * 8 + i;
        float4 a4 = s_ygT[j];
        float w = W2[j * 32 + o];
        acc2.x = fmaf(a4.x, w, acc2.x);
        acc2.y = fmaf(a4.y, w, acc2.y);
        acc2.z = fmaf(a4.z, w, acc2.z);
        acc2.w = fmaf(a4.w, w, acc2.w);
    }
    s_ep[s][o] = acc2;
    __syncthreads();
    if (t < 32) {
        float4 p0 = s_ep[0][t], p1 = s_ep[1][t], p2 = s_ep[2][t], p3 = s_ep[3][t];
        float* op = out + (size_t)n * 128;
        op[t]      = p0.x + p1.x + p2.x + p3.x;
        op[t + 32] = p0.y + p1.y + p2.y + p3.y;
        op[t + 64] = p0.z + p1.z + p2.z + p3.z;
        op[t + 96] = p0.w + p1.w + p2.w + p3.w;
    }
}

// ---------------- launch ----------------
extern "C" void kernel_launch(void* const* d_in, const int* in_sizes, int n_in,
                              void* d_out, int out_size)
{
    const float* rots     = (const float*)d_in[0];
    const float* trans    = (const float*)d_in[1];
    const float* node_emb = (const float*)d_in[2];
    const unsigned char* xm = (const unsigned char*)d_in[4];
    const unsigned char* nm = (const unsigned char*)d_in[5];
    const float* Wa = (const float*)d_in[6];
    const float* av = (const float*)d_in[7];
    const float* Wv = (const float*)d_in[8];
    const float* Wo = (const float*)d_in[9];
    const float* Wg = (const float*)d_in[10];
    const float* W2 = (const float*)d_in[11];
    float* out = (float*)d_out;

    k_prep<<<2048 + 1023 + 1024 + TB, 128>>>(trans, rots, node_emb, xm, nm, Wa, Wv);
    k_main<<<NN, 128>>>(av, Wo, Wg, W2, out);
}

// round 15
// speedup vs baseline: 2.6548x; 1.0399x over previous
#include <cuda_runtime.h>
#include <cuda_fp16.h>
#include <math.h>
#include <stddef.h>

#define NN 8192
#define LL 512
#define KK 30
#define TB 1024                 // rbf table bins over [0,24)
#define TB_SCALE (1024.0f / 24.0f)

typedef unsigned long long ull;

// ---------------- packed f32x2 helpers (used in prep only) ----------------
__device__ __forceinline__ ull pk2(float a, float b) {
    ull r; asm("mov.b64 %0, {%1,%2};" : "=l"(r) : "f"(a), "f"(b)); return r;
}
__device__ __forceinline__ void upk2(ull v, float& a, float& b) {
    asm("mov.b64 {%0,%1}, %2;" : "=f"(a), "=f"(b) : "l"(v));
}
__device__ __forceinline__ ull fma2(ull x, ull y, ull a) {
    ull r; asm("fma.rn.f32x2 %0, %1, %2, %3;" : "=l"(r) : "l"(x), "l"(y), "l"(a));
    return r;
}

// ---------------- device scratch ----------------
__device__ int      g_knn [NN * KK];
__device__ float    g_dist[NN * KK];
__device__ float    g_Psrc[NN * 128];
__device__ float    g_Ptgt[NN * 128];
__device__ float2   g_Vnode2[NN * 128];   // elem i: pair rows r,r+2 (fp32 — precision)
__device__ __half   g_posAH[1023 * 128];  // fp16 pos-emb table
__device__ unsigned g_rbfTH[TB * 128];    // half2{T[dd][c], T[dd+1][c]-T[dd][c]}

// ============ merged prep: knn | posA | node | rbf-table by blockIdx ========
__global__ void k_prep(const float* __restrict__ trans,
                       const float* __restrict__ rots,
                       const float* __restrict__ node_emb,
                       const unsigned char* __restrict__ xm,
                       const unsigned char* __restrict__ nm,
                       const float* __restrict__ Wa,
                       const float* __restrict__ Wv)
{
    __shared__ __align__(16) char u_smem[11520];  // pos(6144) / spill(11520) / semb(4608)
    __shared__ float trig[32];
    __shared__ int   s_u8;
    int bid = blockIdx.x, t = threadIdx.x;

    if (bid < 2048) {
        // ---------- kNN: 4 targets/block, warp each; sort + redux extract ----
        float* sx = (float*)u_smem;           // [512]
        float* sy = sx + LL;
        float* sz = sy + LL;
        int g0 = bid * 4;
        int base = (g0 >> 9) << 9;
        for (int i = t; i < LL; i += 128) {
            const float* p = trans + (size_t)(base + i) * 3;
            sx[i] = p[0]; sy[i] = p[1]; sz[i] = p[2];
        }
        __syncthreads();
        int warp = t >> 5, lane = t & 31;
        int tgt = g0 + warp;
        int tl = tgt & 511;
        float px = sx[tl], py = sy[tl], pz = sz[tl];

        unsigned key[16]; int idx[16];
#pragma unroll
        for (int q = 0; q < 16; q++) {
            int c = lane + (q << 5);
            float dx = sx[c] - px, dy = sy[c] - py, dz = sz[c] - pz;
            float d2 = dx * dx + dy * dy + dz * dz;
            if (c == tl) d2 = 1e30f;
            key[q] = __float_as_uint(d2);
            idx[q] = c;
        }
        __syncthreads();   // all warps done reading positions before spill
        // Batcher odd-even mergesort, ascending by (key, idx)
#pragma unroll
        for (int p = 1; p < 16; p <<= 1) {
#pragma unroll
            for (int k = p; k >= 1; k >>= 1) {
#pragma unroll
                for (int j = k % p; j + k < 16; j += 2 * k) {
#pragma unroll
                    for (int i = 0; i < k; i++) {
                        int a = i + j, b = i + j + k;
                        if (b < 16 && (a / (2 * p)) == (b / (2 * p))) {
                            bool sw = (key[a] > key[b]) ||
                                      (key[a] == key[b] && idx[a] > idx[b]);
                            unsigned ka = sw ? key[b] : key[a];
                            unsigned kb = sw ? key[a] : key[b];
                            int ia = sw ? idx[b] : idx[a];
                            int ib = sw ? idx[a] : idx[b];
                            key[a] = ka; key[b] = kb; idx[a] = ia; idx[b] = ib;
                        }
                    }
                }
            }
        }
        unsigned* skey = (unsigned*)u_smem;                       // [4*15*32]
        unsigned short* sidx = (unsigned short*)(u_smem + 7680);  // [4*15*32]
        int lb = warp * 480 + lane;
#pragma unroll
        for (int q = 1; q < 16; q++) {
            skey[lb + (q - 1) * 32] = key[q];
            sidx[lb + (q - 1) * 32] = (unsigned short)idx[q];
        }
        unsigned ck = key[0]; int ci = idx[0];
        int ptr = 0;
        for (int it = 0; it < KK; it++) {
            unsigned mv = __reduce_min_sync(0xffffffffu, ck);
            unsigned ti = (ck == mv) ? (unsigned)ci : 0xffffffffu;
            unsigned mi = __reduce_min_sync(0xffffffffu, ti);
            if (lane == 0) {
                g_knn [tgt * KK + it] = base + (int)mi;
                g_dist[tgt * KK + it] = sqrtf(__uint_as_float(mv));
            }
            if (ck == mv && (unsigned)ci == mi) {
                if (ptr < 15) {
                    ck = skey[lb + ptr * 32];
                    ci = (int)sidx[lb + ptr * 32];
                    ptr++;
                } else ck = 0xffffffffu;
            }
        }
    } else if (bid < 2048 + 1023) {
        // ---------- posA table (fp16) ----------
        int dd = bid - 2048;
        float delta = (float)(dd - 511);
        if (t < 8) {
            float freq = expf(-(float)(2 * t) * (9.210340371976184f / 16.0f));
            float ang = delta * freq;
            trig[t]     = cosf(ang);
            trig[8 + t] = sinf(ang);
        }
        __syncthreads();
        float s = 0.f;
#pragma unroll
        for (int j = 0; j < 8; j++) {
            s = fmaf(trig[j],     Wa[(86 + j) * 128 + t], s);
            s = fmaf(trig[8 + j], Wa[(94 + j) * 128 + t], s);
        }
        g_posAH[dd * 128 + t] = __float2half(s);
    } else if (bid < 2048 + 1023 + 1024) {
        // ---------- node precompute: 8 nodes / block ----------
        float (*semb)[4][36] = (float (*)[4][36])u_smem;
        int n0 = (bid - (2048 + 1023)) * 8;
        if (t < 64) {
            int any = 0;
#pragma unroll
            for (int j = 1; j < 4; j++) any |= (int)xm[4 * t + j];
            unsigned b = __ballot_sync(0xffffffffu, any != 0);
            if (t == 0) s_u8 = (b != 0u) ? 1 : 0;
        }
        __syncthreads();
        int u8 = s_u8;
        for (int m = 0; m < 8; m++) {
            int n = n0 + m;
            int r = t >> 5, c = t & 31;
            semb[m][r][c] = node_emb[n * 128 + t];
            if (t == 0) {
                const float* R = rots + n * 9;
                const float bx0 = -0.525f, by0 = 1.363f, bx2 = 1.526f;
#pragma unroll
                for (int i = 0; i < 3; i++) {
                    float r0 = R[i * 3 + 0], r1 = R[i * 3 + 1];
                    semb[m][1 + i][32 + 0] = r0 * bx0 + r1 * by0;
                    semb[m][1 + i][32 + 1] = 0.f;
                    semb[m][1 + i][32 + 2] = r0 * bx2;
                }
                int xv = u8 ? (int)xm[n] : (int)xm[n * 4];
                int nv = u8 ? (int)nm[n] : (int)nm[n * 4];
                semb[m][0][32] = 0.f;
                semb[m][0][33] = 0.f;
                semb[m][0][34] = (nv && !xv) ? 1.f : 0.f;
            }
        }
        __syncthreads();
        ull acc2[8];
#pragma unroll
        for (int m = 0; m < 8; m++) acc2[m] = 0ull;
        for (int ch = 0; ch < 35; ch++) {
            ull w2 = pk2(Wa[ch * 128 + t], Wa[(35 + ch) * 128 + t]);
#pragma unroll
            for (int m = 0; m < 8; m++) {
                float e0 = semb[m][0][ch];
                acc2[m] = fma2(pk2(e0, e0), w2, acc2[m]);
            }
        }
#pragma unroll
        for (int m = 0; m < 8; m++) {
            float s, tt; upk2(acc2[m], s, tt);
            g_Psrc[(n0 + m) * 128 + t] = s;
            g_Ptgt[(n0 + m) * 128 + t] = tt;
        }
        int c = t & 63, r0 = t >> 6;
        ull v2[8];
#pragma unroll
        for (int m = 0; m < 8; m++) v2[m] = 0ull;
        for (int ch = 0; ch < 35; ch++) {
            float w = Wv[ch * 64 + c];
            ull wd = pk2(w, w);
#pragma unroll
            for (int m = 0; m < 8; m++)
                v2[m] = fma2(pk2(semb[m][r0][ch], semb[m][r0 + 2][ch]), wd, v2[m]);
        }
#pragma unroll
        for (int m = 0; m < 8; m++) {
            float a, b; upk2(v2[m], a, b);
            g_Vnode2[(n0 + m) * 128 + t] = make_float2(a, b);
        }
    } else {
        // ---------- rbf lerp table: row dd -> half2{T(dd), T(dd+1)-T(dd)} ----
        int dd = bid - (2048 + 1023 + 1024);      // 0..TB-1
        if (t < 32) {
            int j = t & 15;
            float dval = (float)(dd + (t >> 4)) * (24.0f / (float)TB);
            float x = (dval - (float)j * (20.0f / 15.0f)) * 0.8f;
            trig[t] = __expf(-x * x);
        }
        __syncthreads();
        float s0 = 0.f, s1 = 0.f;
#pragma unroll
        for (int j = 0; j < 16; j++) {
            float w = Wa[(70 + j) * 128 + t];
            s0 = fmaf(trig[j],      w, s0);
            s1 = fmaf(trig[16 + j], w, s1);
        }
        __half2 hv = __floats2half2_rn(s0, s1 - s0);
        g_rbfTH[dd * 128 + t] = *reinterpret_cast<unsigned*>(&hv);
    }
}

// ================= main kernel: one block per target node ===================
// channel-pair layout: group g = t>>6 handles edges 2*it+g; lane-in-group
// c = t&63 owns channels (2c, 2c+1).
__global__ void __launch_bounds__(128)
k_main(const float* __restrict__ avec,
       const float* __restrict__ Wo,
       const float* __restrict__ Wg,
       const float* __restrict__ W2,
       float* __restrict__ out)
{
    __shared__ __align__(16) float4 s_meta[KK];       // {off64, toff64, frac, valid}
    __shared__ float s_logit[KK][8];                  // final per-head logits
    __shared__ float s_alphaT[8][32];                 // [head][edge]
    __shared__ __align__(16) float4 s_vp[2][64];      // value partials per group
    __shared__ __align__(16) float s_aggT[64][4];     // transposed aggregate
    __shared__ __align__(16) float4 s_ep[4][32];      // epilogue partials
    __shared__ __align__(16) float4 s_ygT[32];        // gated y, transposed
    __shared__ float s_y0[32];

    int n = blockIdx.x, t = threadIdx.x;
    int g = t >> 6, c = t & 63;

    if (t < KK) {
        int s = g_knn[n * KK + t];
        float d = g_dist[n * KK + t];
        float valid = (isfinite(d) && d > 1e-3f) ? 1.f : 0.f;
        float u = fminf(d * TB_SCALE, (float)(TB - 2) + 0.999f);
        u = fmaxf(u, 0.f);
        int i = (int)u;
        s_meta[t] = make_float4(__int_as_float(s << 6),     // src*64
                                __int_as_float(i << 6),     // tidx*64
                                u - (float)i, valid);
    }
    float2 ptgt2 = reinterpret_cast<const float2*>(g_Ptgt)[n * 64 + c];
    float2 av2   = reinterpret_cast<const float2*>(avec)[c];
    const float2*  psrc2 = reinterpret_cast<const float2*>(g_Psrc);
    const __half2* posA2 = reinterpret_cast<const __half2*>(g_posAH)
                           + (ptrdiff_t)(511 - n) * 64;
    const uint2*   rbfH4 = reinterpret_cast<const uint2*>(g_rbfTH);
    const float4*  vno4  = reinterpret_cast<const float4*>(g_Vnode2);
    __syncthreads();

    // ---- logits: 2 edges in parallel (one per 64-thread group) ----
#pragma unroll 3
    for (int it = 0; it < KK / 2; it++) {
        int e = 2 * it + g;
        float4 m = s_meta[e];
        int off  = __float_as_int(m.x);
        int toff = __float_as_int(m.y);
        float2 ps = psrc2[off + c];
        float2 pa = __half22float2(posA2[off + c]);
        uint2 rv = rbfH4[toff + c];                   // {T0,dT0},{T1,dT1} for chs 2c,2c+1
        float2 f0 = __half22float2(*reinterpret_cast<__half2*>(&rv.x));
        float2 f1 = __half22float2(*reinterpret_cast<__half2*>(&rv.y));
        float a0 = ptgt2.x + ps.x + pa.x + fmaf(m.z, f0.y, f0.x);
        float a1 = ptgt2.y + ps.y + pa.y + fmaf(m.z, f1.y, f1.x);
        float h0 = a0 * __fdividef(1.f, 1.f + __expf(-a0));   // silu
        float h1 = a1 * __fdividef(1.f, 1.f + __expf(-a1));
        float p = h0 * av2.x + h1 * av2.y;
        p += __shfl_xor_sync(0xffffffffu, p, 1);
        p += __shfl_xor_sync(0xffffffffu, p, 2);
        p += __shfl_xor_sync(0xffffffffu, p, 4);
        if ((c & 7) == 0)
            s_logit[e][c >> 3] = p;       // full 16-channel head sum
    }
    __syncthreads();

    // ---- softmax (warp 0: 4 lanes per head) ----
    if (t < 32) {
        int h = t >> 2, q = t & 3;
        float lg[8], vv[8];
        float mx = -1e30f;
        int cnt = 0;
        for (int e = q; e < KK; e += 4, cnt++) {
            float s = s_logit[e][h];
            float valid = s_meta[e].w;
            float l = (s > 0.f) ? s : 0.2f * s;      // leaky_relu 0.2
            l = (valid > 0.f) ? l : -1e9f;
            lg[cnt] = l; vv[cnt] = valid;
            mx = fmaxf(mx, l);
        }
        mx = fmaxf(mx, __shfl_xor_sync(0xffffffffu, mx, 1));
        mx = fmaxf(mx, __shfl_xor_sync(0xffffffffu, mx, 2));
        float den = 0.f;
        cnt = 0;
        for (int e = q; e < KK; e += 4, cnt++) {
            float ex = __expf(lg[cnt] - mx) * vv[cnt];
            s_alphaT[h][e] = ex;
            den += ex;
        }
        den += __shfl_xor_sync(0xffffffffu, den, 1);
        den += __shfl_xor_sync(0xffffffffu, den, 2);
        float inv = __fdividef(1.f, den + 1e-9f);
        for (int e = q; e < KK; e += 4)
            s_alphaT[h][e] *= inv;
    }
    __syncthreads();

    // ---- value aggregation: 2 edges in parallel, float4 Vnode loads ----
    {
        int c0 = (2 * c) & 63;
        int h = c0 >> 3;
        float4 acc = make_float4(0.f, 0.f, 0.f, 0.f);
#pragma unroll 3
        for (int it = 0; it < KK / 2; it++) {
            int e = 2 * it + g;
            int off = __float_as_int(s_meta[e].x);   // src*64
            float al = s_alphaT[h][e];
            float4 v = vno4[off + c];
            acc.x = fmaf(al, v.x, acc.x);
            acc.y = fmaf(al, v.y, acc.y);
            acc.z = fmaf(al, v.z, acc.z);
            acc.w = fmaf(al, v.w, acc.w);
        }
        s_vp[g][c] = acc;
    }
    __syncthreads();
    if (t < 64) {
        float4 p0 = s_vp[0][t], p1 = s_vp[1][t];
        int c0 = (2 * t) & 63;
        int r  = (2 * t) >> 6;                       // 0 or 1
        s_aggT[c0][r]         = p0.x + p1.x;
        s_aggT[c0][r + 2]     = p0.y + p1.y;
        s_aggT[c0 + 1][r]     = p0.z + p1.z;
        s_aggT[c0 + 1][r + 2] = p0.w + p1.w;
    }
    __syncthreads();

    // ---- epilogue: y = agg @ Wo (4 outputs/thread), gate, W2 ----
    int o = t & 31, s = t >> 5;
    const float4* aggT4 = reinterpret_cast<const float4*>(s_aggT);
    float4 acc4 = make_float4(0.f, 0.f, 0.f, 0.f);
#pragma unroll
    for (int i = 0; i < 16; i++) {
        int cc = s * 16 + i;
        float4 a4 = aggT4[cc];
        float w = Wo[cc * 32 + o];
        acc4.x = fmaf(a4.x, w, acc4.x);
        acc4.y = fmaf(a4.y, w, acc4.y);
        acc4.z = fmaf(a4.z, w, acc4.z);
        acc4.w = fmaf(a4.w, w, acc4.w);
    }
    s_ep[s][o] = acc4;
    __syncthreads();
    float4 y4;
    if (t < 32) {
        float4 p0 = s_ep[0][t], p1 = s_ep[1][t], p2 = s_ep[2][t], p3 = s_ep[3][t];
        y4.x = p0.x + p1.x + p2.x + p3.x;
        y4.y = p0.y + p1.y + p2.y + p3.y;
        y4.z = p0.z + p1.z + p2.z + p3.z;
        y4.w = p0.w + p1.w + p2.w + p3.w;
        s_y0[t] = y4.x;
    }
    __syncthreads();
    if (t < 32) {
        float gg = 0.f;
#pragma unroll
        for (int j = 0; j < 32; j++) gg = fmaf(s_y0[j], Wg[j * 32 + t], gg);
        gg = gg * __fdividef(1.f, 1.f + __expf(-gg));  // silu gate
        y4.x *= gg; y4.y *= gg; y4.z *= gg; y4.w *= gg;
        s_ygT[t] = y4;
    }
    __syncthreads();
    float4 acc2 = make_float4(0.f, 0.f, 0.f, 0.f);
#pragma unroll
    for (int i = 0; i < 8; i++) {
        int j = s * 8 + i;
        float4 a4 = s_ygT[j];
        float w = W2[j * 32 + o];
        acc2.x = fmaf(a4.x, w, acc2.x);
        acc2.y = fmaf(a4.y, w, acc2.y);
        acc2.z = fmaf(a4.z, w, acc2.z);
        acc2.w = fmaf(a4.w, w, acc2.w);
    }
    s_ep[s][o] = acc2;
    __syncthreads();
    if (t < 32) {
        float4 p0 = s_ep[0][t], p1 = s_ep[1][t], p2 = s_ep[2][t], p3 = s_ep[3][t];
        float* op = out + (size_t)n * 128;
        op[t]      = p0.x + p1.x + p2.x + p3.x;
        op[t + 32] = p0.y + p1.y + p2.y + p3.y;
        op[t + 64] = p0.z + p1.z + p2.z + p3.z;
        op[t + 96] = p0.w + p1.w + p2.w + p3.w;
    }
}

// ---------------- launch ----------------
extern "C" void kernel_launch(void* const* d_in, const int* in_sizes, int n_in,
                              void* d_out, int out_size)
{
    const float* rots     = (const float*)d_in[0];
    const float* trans    = (const float*)d_in[1];
    const float* node_emb = (const float*)d_in[2];
    const unsigned char* xm = (const unsigned char*)d_in[4];
    const unsigned char* nm = (const unsigned char*)d_in[5];
    const float* Wa = (const float*)d_in[6];
    const float* av = (const float*)d_in[7];
    const float* Wv = (const float*)d_in[8];
    const float* Wo = (const float*)d_in[9];
    const float* Wg = (const float*)d_in[10];
    const float* W2 = (const float*)d_in[11];
    float* out = (float*)d_out;

    k_prep<<<2048 + 1023 + 1024 + TB, 128>>>(trans, rots, node_emb, xm, nm, Wa, Wv);
    k_main<<<NN, 128>>>(av, Wo, Wg, W2, out);
}

// round 16
// speedup vs baseline: 2.6969x; 1.0159x over previous
#include <cuda_runtime.h>
#include <cuda_fp16.h>
#include <math.h>
#include <stddef.h>

#define NN 8192
#define LL 512
#define KK 30
#define TB 1024                 // rbf table bins over [0,24)
#define TB_SCALE (1024.0f / 24.0f)

// ---------------- device scratch ----------------
__device__ int      g_knn [NN * KK];
__device__ float    g_dist[NN * KK];
__device__ __half   g_PsrcH[NN * 128];    // fp16 src logit term
__device__ float    g_Ptgt[NN * 128];     // fp32 tgt logit term
__device__ float2   g_Vnode2[NN * 128];   // elem i: pair rows r,r+2 (fp32 — precision)
__device__ __half   g_posAH[1023 * 128];  // fp16 pos-emb table
__device__ unsigned g_rbfTH[TB * 128];    // half2{T[dd][c], T[dd+1][c]-T[dd][c]}

// grid layout: [0,2048) knn | [2048,2176) posA(8 rows/blk) |
//              [2176,3200) node | [3200,3328) rbf(8 rows/blk)
#define B_KNN   2048
#define B_POSA  (B_KNN + 128)
#define B_NODE  (B_POSA + 1024)
#define B_RBF   (B_NODE + 128)

__global__ void k_prep(const float* __restrict__ trans,
                       const float* __restrict__ rots,
                       const float* __restrict__ node_emb,
                       const unsigned char* __restrict__ xm,
                       const unsigned char* __restrict__ nm,
                       const float* __restrict__ Wa,
                       const float* __restrict__ Wv)
{
    __shared__ __align__(16) char u_smem[11520];  // pos/spill/semb/trig union
    __shared__ int s_u8;
    int bid = blockIdx.x, t = threadIdx.x;

    if (bid < B_KNN) {
        // ---------- kNN: 4 targets/block, warp each; sort + redux extract ----
        float* sx = (float*)u_smem;           // [512]
        float* sy = sx + LL;
        float* sz = sy + LL;
        int g0 = bid * 4;
        int base = (g0 >> 9) << 9;
        for (int i = t; i < LL; i += 128) {
            const float* p = trans + (size_t)(base + i) * 3;
            sx[i] = p[0]; sy[i] = p[1]; sz[i] = p[2];
        }
        __syncthreads();
        int warp = t >> 5, lane = t & 31;
        int tgt = g0 + warp;
        int tl = tgt & 511;
        float px = sx[tl], py = sy[tl], pz = sz[tl];

        unsigned key[16]; int idx[16];
#pragma unroll
        for (int q = 0; q < 16; q++) {
            int c = lane + (q << 5);
            float dx = sx[c] - px, dy = sy[c] - py, dz = sz[c] - pz;
            float d2 = dx * dx + dy * dy + dz * dz;
            if (c == tl) d2 = 1e30f;
            key[q] = __float_as_uint(d2);
            idx[q] = c;
        }
        __syncthreads();   // all warps done reading positions before spill
        // Batcher odd-even mergesort, ascending by (key, idx)
#pragma unroll
        for (int p = 1; p < 16; p <<= 1) {
#pragma unroll
            for (int k = p; k >= 1; k >>= 1) {
#pragma unroll
                for (int j = k % p; j + k < 16; j += 2 * k) {
#pragma unroll
                    for (int i = 0; i < k; i++) {
                        int a = i + j, b = i + j + k;
                        if (b < 16 && (a / (2 * p)) == (b / (2 * p))) {
                            bool sw = (key[a] > key[b]) ||
                                      (key[a] == key[b] && idx[a] > idx[b]);
                            unsigned ka = sw ? key[b] : key[a];
                            unsigned kb = sw ? key[a] : key[b];
                            int ia = sw ? idx[b] : idx[a];
                            int ib = sw ? idx[a] : idx[b];
                            key[a] = ka; key[b] = kb; idx[a] = ia; idx[b] = ib;
                        }
                    }
                }
            }
        }
        unsigned* skey = (unsigned*)u_smem;                       // [4*15*32]
        unsigned short* sidx = (unsigned short*)(u_smem + 7680);  // [4*15*32]
        int lb = warp * 480 + lane;
#pragma unroll
        for (int q = 1; q < 16; q++) {
            skey[lb + (q - 1) * 32] = key[q];
            sidx[lb + (q - 1) * 32] = (unsigned short)idx[q];
        }
        unsigned ck = key[0]; int ci = idx[0];
        int ptr = 0;
        for (int it = 0; it < KK; it++) {
            unsigned mv = __reduce_min_sync(0xffffffffu, ck);
            unsigned ti = (ck == mv) ? (unsigned)ci : 0xffffffffu;
            unsigned mi = __reduce_min_sync(0xffffffffu, ti);
            if (lane == 0) {
                g_knn [tgt * KK + it] = base + (int)mi;
                g_dist[tgt * KK + it] = sqrtf(__uint_as_float(mv));
            }
            if (ck == mv && (unsigned)ci == mi) {
                if (ptr < 15) {
                    ck = skey[lb + ptr * 32];
                    ci = (int)sidx[lb + ptr * 32];
                    ptr++;
                } else ck = 0xffffffffu;
            }
        }
    } else if (bid < B_POSA) {
        // ---------- posA table: 8 rows / block ----------
        float (*s_trig)[16] = (float (*)[16])u_smem;   // [8][16]
        int dd0 = (bid - B_KNN) * 8;
        {
            int r = t >> 4, i = t & 15, j = i & 7;
            float delta = (float)(dd0 + r - 511);
            float freq = expf(-(float)(2 * j) * (9.210340371976184f / 16.0f));
            float ang = delta * freq;
            s_trig[r][i] = (i < 8) ? cosf(ang) : sinf(ang);
        }
        float wc[8], ws[8];
#pragma unroll
        for (int j = 0; j < 8; j++) {
            wc[j] = Wa[(86 + j) * 128 + t];
            ws[j] = Wa[(94 + j) * 128 + t];
        }
        __syncthreads();
#pragma unroll
        for (int r = 0; r < 8; r++) {
            int dd = dd0 + r;
            if (dd < 1023) {
                float s = 0.f;
#pragma unroll
                for (int j = 0; j < 8; j++) {
                    s = fmaf(s_trig[r][j],     wc[j], s);
                    s = fmaf(s_trig[r][8 + j], ws[j], s);
                }
                g_posAH[dd * 128 + t] = __float2half(s);
            }
        }
    } else if (bid < B_NODE) {
        // ---------- node precompute: 8 nodes / block (plain fmaf) ----------
        float (*semb)[4][36] = (float (*)[4][36])u_smem;
        int n0 = (bid - B_POSA) * 8;
        if (t < 64) {
            int any = 0;
#pragma unroll
            for (int j = 1; j < 4; j++) any |= (int)xm[4 * t + j];
            unsigned b = __ballot_sync(0xffffffffu, any != 0);
            if (t == 0) s_u8 = (b != 0u) ? 1 : 0;
        }
        __syncthreads();
        int u8 = s_u8;
        for (int m = 0; m < 8; m++) {
            int n = n0 + m;
            int r = t >> 5, c = t & 31;
            semb[m][r][c] = node_emb[n * 128 + t];
            if (t == 0) {
                const float* R = rots + n * 9;
                const float bx0 = -0.525f, by0 = 1.363f, bx2 = 1.526f;
#pragma unroll
                for (int i = 0; i < 3; i++) {
                    float r0 = R[i * 3 + 0], r1 = R[i * 3 + 1];
                    semb[m][1 + i][32 + 0] = r0 * bx0 + r1 * by0;
                    semb[m][1 + i][32 + 1] = 0.f;
                    semb[m][1 + i][32 + 2] = r0 * bx2;
                }
                int xv = u8 ? (int)xm[n] : (int)xm[n * 4];
                int nv = u8 ? (int)nm[n] : (int)nm[n * 4];
                semb[m][0][32] = 0.f;
                semb[m][0][33] = 0.f;
                semb[m][0][34] = (nv && !xv) ? 1.f : 0.f;
            }
        }
        __syncthreads();
        float accS[8], accT[8];
#pragma unroll
        for (int m = 0; m < 8; m++) { accS[m] = 0.f; accT[m] = 0.f; }
        for (int ch = 0; ch < 35; ch++) {
            float wsrc = Wa[ch * 128 + t];
            float wtgt = Wa[(35 + ch) * 128 + t];
#pragma unroll
            for (int m = 0; m < 8; m++) {
                float e0 = semb[m][0][ch];
                accS[m] = fmaf(e0, wsrc, accS[m]);
                accT[m] = fmaf(e0, wtgt, accT[m]);
            }
        }
#pragma unroll
        for (int m = 0; m < 8; m++) {
            g_PsrcH[(n0 + m) * 128 + t] = __float2half(accS[m]);
            g_Ptgt [(n0 + m) * 128 + t] = accT[m];
        }
        int c = t & 63, r0 = t >> 6;
        float v0[8], v1[8];
#pragma unroll
        for (int m = 0; m < 8; m++) { v0[m] = 0.f; v1[m] = 0.f; }
        for (int ch = 0; ch < 35; ch++) {
            float w = Wv[ch * 64 + c];
#pragma unroll
            for (int m = 0; m < 8; m++) {
                v0[m] = fmaf(semb[m][r0][ch],     w, v0[m]);
                v1[m] = fmaf(semb[m][r0 + 2][ch], w, v1[m]);
            }
        }
#pragma unroll
        for (int m = 0; m < 8; m++)
            g_Vnode2[(n0 + m) * 128 + t] = make_float2(v0[m], v1[m]);
    } else {
        // ---------- rbf lerp table: 8 rows / block ----------
        float (*s_e)[16] = (float (*)[16])u_smem;      // [9][16]
        int dd0 = (bid - B_NODE) * 8;
        for (int i = t; i < 9 * 16; i += 128) {
            int r = i >> 4, j = i & 15;
            float dval = (float)(dd0 + r) * (24.0f / (float)TB);
            float x = (dval - (float)j * (20.0f / 15.0f)) * 0.8f;
            s_e[r][j] = __expf(-x * x);
        }
        float warb[16];
#pragma unroll
        for (int j = 0; j < 16; j++) warb[j] = Wa[(70 + j) * 128 + t];
        __syncthreads();
#pragma unroll
        for (int r = 0; r < 8; r++) {
            float s0 = 0.f, s1 = 0.f;
#pragma unroll
            for (int j = 0; j < 16; j++) {
                s0 = fmaf(s_e[r][j],     warb[j], s0);
                s1 = fmaf(s_e[r + 1][j], warb[j], s1);
            }
            __half2 hv = __floats2half2_rn(s0, s1 - s0);
            g_rbfTH[(dd0 + r) * 128 + t] = *reinterpret_cast<unsigned*>(&hv);
        }
    }
}

// ================= main kernel: one block per target node ===================
// channel-pair layout: group g = t>>6 handles edges 2*it+g; lane-in-group
// c = t&63 owns channels (2c, 2c+1).
__global__ void __launch_bounds__(128)
k_main(const float* __restrict__ avec,
       const float* __restrict__ Wo,
       const float* __restrict__ Wg,
       const float* __restrict__ W2,
       float* __restrict__ out)
{
    __shared__ __align__(16) float4 s_meta[KK];       // {off64, toff64, frac, valid}
    __shared__ float s_logit[KK][8];                  // final per-head logits
    __shared__ float s_alphaT[8][32];                 // [head][edge]
    __shared__ __align__(16) float4 s_vp[2][64];      // value partials per group
    __shared__ __align__(16) float s_aggT[64][4];     // transposed aggregate
    __shared__ __align__(16) float4 s_ep[4][32];      // epilogue partials
    __shared__ __align__(16) float4 s_ygT[32];        // gated y, transposed
    __shared__ float s_y0[32];

    int n = blockIdx.x, t = threadIdx.x;
    int g = t >> 6, c = t & 63;

    if (t < KK) {
        int s = g_knn[n * KK + t];
        float d = g_dist[n * KK + t];
        float valid = (isfinite(d) && d > 1e-3f) ? 1.f : 0.f;
        float u = fminf(d * TB_SCALE, (float)(TB - 2) + 0.999f);
        u = fmaxf(u, 0.f);
        int i = (int)u;
        s_meta[t] = make_float4(__int_as_float(s << 6),     // src*64
                                __int_as_float(i << 6),     // tidx*64
                                u - (float)i, valid);
    }
    float2 ptgt2 = reinterpret_cast<const float2*>(g_Ptgt)[n * 64 + c];
    float2 av2   = reinterpret_cast<const float2*>(avec)[c];
    const __half2* psrcH = reinterpret_cast<const __half2*>(g_PsrcH);
    const __half2* posA2 = reinterpret_cast<const __half2*>(g_posAH)
                           + (ptrdiff_t)(511 - n) * 64;
    const uint2*   rbfH4 = reinterpret_cast<const uint2*>(g_rbfTH);
    const float4*  vno4  = reinterpret_cast<const float4*>(g_Vnode2);
    __syncthreads();

    // ---- logits: 2 edges in parallel (one per 64-thread group) ----
#pragma unroll 3
    for (int it = 0; it < KK / 2; it++) {
        int e = 2 * it + g;
        float4 m = s_meta[e];
        int off  = __float_as_int(m.x);
        int toff = __float_as_int(m.y);
        float2 ps = __half22float2(psrcH[off + c]);
        float2 pa = __half22float2(posA2[off + c]);
        uint2 rv = rbfH4[toff + c];                   // {T0,dT0},{T1,dT1} for chs 2c,2c+1
        float2 f0 = __half22float2(*reinterpret_cast<__half2*>(&rv.x));
        float2 f1 = __half22float2(*reinterpret_cast<__half2*>(&rv.y));
        float a0 = ptgt2.x + ps.x + pa.x + fmaf(m.z, f0.y, f0.x);
        float a1 = ptgt2.y + ps.y + pa.y + fmaf(m.z, f1.y, f1.x);
        float h0 = a0 * __fdividef(1.f, 1.f + __expf(-a0));   // silu
        float h1 = a1 * __fdividef(1.f, 1.f + __expf(-a1));
        float p = h0 * av2.x + h1 * av2.y;
        p += __shfl_xor_sync(0xffffffffu, p, 1);
        p += __shfl_xor_sync(0xffffffffu, p, 2);
        p += __shfl_xor_sync(0xffffffffu, p, 4);
        if ((c & 7) == 0)
            s_logit[e][c >> 3] = p;       // full 16-channel head sum
    }
    __syncthreads();

    // ---- softmax (warp 0: 4 lanes per head) ----
    if (t < 32) {
        int h = t >> 2, q = t & 3;
        float lg[8], vv[8];
        float mx = -1e30f;
        int cnt = 0;
        for (int e = q; e < KK; e += 4, cnt++) {
            float s = s_logit[e][h];
            float valid = s_meta[e].w;
            float l = (s > 0.f) ? s : 0.2f * s;      // leaky_relu 0.2
            l = (valid > 0.f) ? l : -1e9f;
            lg[cnt] = l; vv[cnt] = valid;
            mx = fmaxf(mx, l);
        }
        mx = fmaxf(mx, __shfl_xor_sync(0xffffffffu, mx, 1));
        mx = fmaxf(mx, __shfl_xor_sync(0xffffffffu, mx, 2));
        float den = 0.f;
        cnt = 0;
        for (int e = q; e < KK; e += 4, cnt++) {
            float ex = __expf(lg[cnt] - mx) * vv[cnt];
            s_alphaT[h][e] = ex;
            den += ex;
        }
        den += __shfl_xor_sync(0xffffffffu, den, 1);
        den += __shfl_xor_sync(0xffffffffu, den, 2);
        float inv = __fdividef(1.f, den + 1e-9f);
        for (int e = q; e < KK; e += 4)
            s_alphaT[h][e] *= inv;
    }
    __syncthreads();

    // ---- value aggregation: 2 edges in parallel, float4 Vnode loads ----
    {
        int c0 = (2 * c) & 63;
        int h = c0 >> 3;
        float4 acc = make_float4(0.f, 0.f, 0.f, 0.f);
#pragma unroll 3
        for (int it = 0; it < KK / 2; it++) {
            int e = 2 * it + g;
            int off = __float_as_int(s_meta[e].x);   // src*64
            float al = s_alphaT[h][e];
            float4 v = vno4[off + c];
            acc.x = fmaf(al, v.x, acc.x);
            acc.y = fmaf(al, v.y, acc.y);
            acc.z = fmaf(al, v.z, acc.z);
            acc.w = fmaf(al, v.w, acc.w);
        }
        s_vp[g][c] = acc;
    }
    __syncthreads();
    if (t < 64) {
        float4 p0 = s_vp[0][t], p1 = s_vp[1][t];
        int c0 = (2 * t) & 63;
        int r  = (2 * t) >> 6;                       // 0 or 1
        s_aggT[c0][r]         = p0.x + p1.x;
        s_aggT[c0][r + 2]     = p0.y + p1.y;
        s_aggT[c0 + 1][r]     = p0.z + p1.z;
        s_aggT[c0 + 1][r + 2] = p0.w + p1.w;
    }
    __syncthreads();

    // ---- epilogue: y = agg @ Wo (4 outputs/thread), gate, W2 ----
    int o = t & 31, s = t >> 5;
    const float4* aggT4 = reinterpret_cast<const float4*>(s_aggT);
    float4 acc4 = make_float4(0.f, 0.f, 0.f, 0.f);
#pragma unroll
    for (int i = 0; i < 16; i++) {
        int cc = s * 16 + i;
        float4 a4 = aggT4[cc];
        float w = Wo[cc * 32 + o];
        acc4.x = fmaf(a4.x, w, acc4.x);
        acc4.y = fmaf(a4.y, w, acc4.y);
        acc4.z = fmaf(a4.z, w, acc4.z);
        acc4.w = fmaf(a4.w, w, acc4.w);
    }
    s_ep[s][o] = acc4;
    __syncthreads();
    float4 y4;
    if (t < 32) {
        float4 p0 = s_ep[0][t], p1 = s_ep[1][t], p2 = s_ep[2][t], p3 = s_ep[3][t];
        y4.x = p0.x + p1.x + p2.x + p3.x;
        y4.y = p0.y + p1.y + p2.y + p3.y;
        y4.z = p0.z + p1.z + p2.z + p3.z;
        y4.w = p0.w + p1.w + p2.w + p3.w;
        s_y0[t] = y4.x;
    }
    __syncthreads();
    if (t < 32) {
        float gg = 0.f;
#pragma unroll
        for (int j = 0; j < 32; j++) gg = fmaf(s_y0[j], Wg[j * 32 + t], gg);
        gg = gg * __fdividef(1.f, 1.f + __expf(-gg));  // silu gate
        y4.x *= gg; y4.y *= gg; y4.z *= gg; y4.w *= gg;
        s_ygT[t] = y4;
    }
    __syncthreads();
    float4 acc2 = make_float4(0.f, 0.f, 0.f, 0.f);
#pragma unroll
    for (int i = 0; i < 8; i++) {
        int j = s * 8 + i;
        float4 a4 = s_ygT[j];
        float w = W2[j * 32 + o];
        acc2.x = fmaf(a4.x, w, acc2.x);
        acc2.y = fmaf(a4.y, w, acc2.y);
        acc2.z = fmaf(a4.z, w, acc2.z);
        acc2.w = fmaf(a4.w, w, acc2.w);
    }
    s_ep[s][o] = acc2;
    __syncthreads();
    if (t < 32) {
        float4 p0 = s_ep[0][t], p1 = s_ep[1][t], p2 = s_ep[2][t], p3 = s_ep[3][t];
        float* op = out + (size_t)n * 128;
        op[t]      = p0.x + p1.x + p2.x + p3.x;
        op[t + 32] = p0.y + p1.y + p2.y + p3.y;
        op[t + 64] = p0.z + p1.z + p2.z + p3.z;
        op[t + 96] = p0.w + p1.w + p2.w + p3.w;
    }
}

// ---------------- launch ----------------
extern "C" void kernel_launch(void* const* d_in, const int* in_sizes, int n_in,
                              void* d_out, int out_size)
{
    const float* rots     = (const float*)d_in[0];
    const float* trans    = (const float*)d_in[1];
    const float* node_emb = (const float*)d_in[2];
    const unsigned char* xm = (const unsigned char*)d_in[4];
    const unsigned char* nm = (const unsigned char*)d_in[5];
    const float* Wa = (const float*)d_in[6];
    const float* av = (const float*)d_in[7];
    const float* Wv = (const float*)d_in[8];
    const float* Wo = (const float*)d_in[9];
    const float* Wg = (const float*)d_in[10];
    const float* W2 = (const float*)d_in[11];
    float* out = (float*)d_out;

    k_prep<<<B_RBF, 128>>>(trans, rots, node_emb, xm, nm, Wa, Wv);
    k_main<<<NN, 128>>>(av, Wo, Wg, W2, out);
}

// round 17
// speedup vs baseline: 2.7992x; 1.0379x over previous
#include <cuda_runtime.h>
#include <cuda_fp16.h>
#include <math.h>
#include <stddef.h>

#define NN 8192
#define LL 512
#define KK 30
#define TB 1024                 // rbf table bins over [0,24)
#define TB_SCALE (1024.0f / 24.0f)

// ---------------- device scratch ----------------
__device__ int      g_knn [NN * KK];
__device__ float    g_dist[NN * KK];
__device__ __half   g_PsrcH[NN * 128];    // fp16 src logit term
__device__ float    g_Ptgt[NN * 128];     // fp32 tgt logit term
__device__ float2   g_Vnode2[NN * 128];   // elem i: pair rows r,r+2 (fp32 — precision)
__device__ __half   g_posAH[1023 * 128];  // fp16 pos-emb table
__device__ unsigned g_rbfTH[TB * 128];    // half2{T[dd][c], T[dd+1][c]-T[dd][c]}

// grid layout: [0,2048) knn | [2048,2176) posA(8 rows/blk) |
//              [2176,3200) node | [3200,3328) rbf(8 rows/blk)
#define B_KNN   2048
#define B_POSA  (B_KNN + 128)
#define B_NODE  (B_POSA + 1024)
#define B_RBF   (B_NODE + 128)

__global__ void k_prep(const float* __restrict__ trans,
                       const float* __restrict__ rots,
                       const float* __restrict__ node_emb,
                       const unsigned char* __restrict__ xm,
                       const unsigned char* __restrict__ nm,
                       const float* __restrict__ Wa,
                       const float* __restrict__ Wv)
{
    __shared__ __align__(16) char u_smem[11520];  // pos/spill/semb/trig union
    __shared__ int s_u8;
    int bid = blockIdx.x, t = threadIdx.x;

    if (bid < B_KNN) {
        // ---------- kNN: 4 targets/block, warp each; sort + redux extract ----
        float* pos = (float*)u_smem;          // [1536] xyz interleaved
        int g0 = bid * 4;
        int base = (g0 >> 9) << 9;
        {   // coalesced float4 load of 512 points (1536 floats = 384 float4)
            const float4* tp = (const float4*)(trans + (size_t)base * 3);
            float4* sp = (float4*)u_smem;
            for (int i = t; i < 384; i += 128) sp[i] = tp[i];
        }
        __syncthreads();
        int warp = t >> 5, lane = t & 31;
        int tgt = g0 + warp;
        int tl = tgt & 511;
        float px = pos[3 * tl], py = pos[3 * tl + 1], pz = pos[3 * tl + 2];

        unsigned key[16]; int idx[16];
#pragma unroll
        for (int q = 0; q < 16; q++) {
            int c = lane + (q << 5);
            float dx = pos[3 * c] - px, dy = pos[3 * c + 1] - py, dz = pos[3 * c + 2] - pz;
            float d2 = dx * dx + dy * dy + dz * dz;
            if (c == tl) d2 = 1e30f;
            key[q] = __float_as_uint(d2);
            idx[q] = c;
        }
        __syncthreads();   // all warps done reading positions before spill
        // Batcher odd-even mergesort, ascending by (key, idx)
#pragma unroll
        for (int p = 1; p < 16; p <<= 1) {
#pragma unroll
            for (int k = p; k >= 1; k >>= 1) {
#pragma unroll
                for (int j = k % p; j + k < 16; j += 2 * k) {
#pragma unroll
                    for (int i = 0; i < k; i++) {
                        int a = i + j, b = i + j + k;
                        if (b < 16 && (a / (2 * p)) == (b / (2 * p))) {
                            bool sw = (key[a] > key[b]) ||
                                      (key[a] == key[b] && idx[a] > idx[b]);
                            unsigned ka = sw ? key[b] : key[a];
                            unsigned kb = sw ? key[a] : key[b];
                            int ia = sw ? idx[b] : idx[a];
                            int ib = sw ? idx[a] : idx[b];
                            key[a] = ka; key[b] = kb; idx[a] = ia; idx[b] = ib;
                        }
                    }
                }
            }
        }
        unsigned* skey = (unsigned*)u_smem;                       // [4*15*32]
        unsigned short* sidx = (unsigned short*)(u_smem + 7680);  // [4*15*32]
        int lb = warp * 480 + lane;
#pragma unroll
        for (int q = 1; q < 16; q++) {
            skey[lb + (q - 1) * 32] = key[q];
            sidx[lb + (q - 1) * 32] = (unsigned short)idx[q];
        }
        unsigned ck = key[0]; int ci = idx[0];
        int ptr = 0;
        for (int it = 0; it < KK; it++) {
            unsigned mv = __reduce_min_sync(0xffffffffu, ck);
            unsigned ti = (ck == mv) ? (unsigned)ci : 0xffffffffu;
            unsigned mi = __reduce_min_sync(0xffffffffu, ti);
            if (lane == 0) {
                g_knn [tgt * KK + it] = base + (int)mi;
                g_dist[tgt * KK + it] = sqrtf(__uint_as_float(mv));
            }
            if (ck == mv && (unsigned)ci == mi) {
                if (ptr < 15) {
                    ck = skey[lb + ptr * 32];
                    ci = (int)sidx[lb + ptr * 32];
                    ptr++;
                } else ck = 0xffffffffu;
            }
        }
    } else if (bid < B_POSA) {
        // ---------- posA table: 8 rows / block ----------
        float (*s_trig)[16] = (float (*)[16])u_smem;   // [8][16]
        int dd0 = (bid - B_KNN) * 8;
        {
            int r = t >> 4, i = t & 15, j = i & 7;
            float delta = (float)(dd0 + r - 511);
            float freq = expf(-(float)(2 * j) * (9.210340371976184f / 16.0f));
            float ang = delta * freq;
            s_trig[r][i] = (i < 8) ? cosf(ang) : sinf(ang);
        }
        float wc[8], ws[8];
#pragma unroll
        for (int j = 0; j < 8; j++) {
            wc[j] = Wa[(86 + j) * 128 + t];
            ws[j] = Wa[(94 + j) * 128 + t];
        }
        __syncthreads();
#pragma unroll
        for (int r = 0; r < 8; r++) {
            int dd = dd0 + r;
            if (dd < 1023) {
                float s = 0.f;
#pragma unroll
                for (int j = 0; j < 8; j++) {
                    s = fmaf(s_trig[r][j],     wc[j], s);
                    s = fmaf(s_trig[r][8 + j], ws[j], s);
                }
                g_posAH[dd * 128 + t] = __float2half(s);
            }
        }
    } else if (bid < B_NODE) {
        // ---------- node precompute: 8 nodes / block (plain fmaf) ----------
        float (*semb)[4][36] = (float (*)[4][36])u_smem;
        int n0 = (bid - B_POSA) * 8;
        if (t < 64) {
            int any = 0;
#pragma unroll
            for (int j = 1; j < 4; j++) any |= (int)xm[4 * t + j];
            unsigned b = __ballot_sync(0xffffffffu, any != 0);
            if (t == 0) s_u8 = (b != 0u) ? 1 : 0;
        }
        __syncthreads();
        int u8 = s_u8;
        for (int m = 0; m < 8; m++) {
            int n = n0 + m;
            int r = t >> 5, c = t & 31;
            semb[m][r][c] = node_emb[n * 128 + t];
            if (t == 0) {
                const float* R = rots + n * 9;
                const float bx0 = -0.525f, by0 = 1.363f, bx2 = 1.526f;
#pragma unroll
                for (int i = 0; i < 3; i++) {
                    float r0 = R[i * 3 + 0], r1 = R[i * 3 + 1];
                    semb[m][1 + i][32 + 0] = r0 * bx0 + r1 * by0;
                    semb[m][1 + i][32 + 1] = 0.f;
                    semb[m][1 + i][32 + 2] = r0 * bx2;
                }
                int xv = u8 ? (int)xm[n] : (int)xm[n * 4];
                int nv = u8 ? (int)nm[n] : (int)nm[n * 4];
                semb[m][0][32] = 0.f;
                semb[m][0][33] = 0.f;
                semb[m][0][34] = (nv && !xv) ? 1.f : 0.f;
            }
        }
        __syncthreads();
        float accS[8], accT[8];
#pragma unroll
        for (int m = 0; m < 8; m++) { accS[m] = 0.f; accT[m] = 0.f; }
        for (int ch = 0; ch < 35; ch++) {
            float wsrc = Wa[ch * 128 + t];
            float wtgt = Wa[(35 + ch) * 128 + t];
#pragma unroll
            for (int m = 0; m < 8; m++) {
                float e0 = semb[m][0][ch];
                accS[m] = fmaf(e0, wsrc, accS[m]);
                accT[m] = fmaf(e0, wtgt, accT[m]);
            }
        }
#pragma unroll
        for (int m = 0; m < 8; m++) {
            g_PsrcH[(n0 + m) * 128 + t] = __float2half(accS[m]);
            g_Ptgt [(n0 + m) * 128 + t] = accT[m];
        }
        int c = t & 63, r0 = t >> 6;
        float v0[8], v1[8];
#pragma unroll
        for (int m = 0; m < 8; m++) { v0[m] = 0.f; v1[m] = 0.f; }
        for (int ch = 0; ch < 35; ch++) {
            float w = Wv[ch * 64 + c];
#pragma unroll
            for (int m = 0; m < 8; m++) {
                v0[m] = fmaf(semb[m][r0][ch],     w, v0[m]);
                v1[m] = fmaf(semb[m][r0 + 2][ch], w, v1[m]);
            }
        }
#pragma unroll
        for (int m = 0; m < 8; m++)
            g_Vnode2[(n0 + m) * 128 + t] = make_float2(v0[m], v1[m]);
    } else {
        // ---------- rbf lerp table: 8 rows / block ----------
        float (*s_e)[16] = (float (*)[16])u_smem;      // [9][16]
        int dd0 = (bid - B_NODE) * 8;
        for (int i = t; i < 9 * 16; i += 128) {
            int r = i >> 4, j = i & 15;
            float dval = (float)(dd0 + r) * (24.0f / (float)TB);
            float x = (dval - (float)j * (20.0f / 15.0f)) * 0.8f;
            s_e[r][j] = __expf(-x * x);
        }
        float warb[16];
#pragma unroll
        for (int j = 0; j < 16; j++) warb[j] = Wa[(70 + j) * 128 + t];
        __syncthreads();
#pragma unroll
        for (int r = 0; r < 8; r++) {
            float s0 = 0.f, s1 = 0.f;
#pragma unroll
            for (int j = 0; j < 16; j++) {
                s0 = fmaf(s_e[r][j],     warb[j], s0);
                s1 = fmaf(s_e[r + 1][j], warb[j], s1);
            }
            __half2 hv = __floats2half2_rn(s0, s1 - s0);
            g_rbfTH[(dd0 + r) * 128 + t] = *reinterpret_cast<unsigned*>(&hv);
        }
    }
}

// ================= main kernel: one block per target node ===================
// 4-way edge parallelism: warp w handles edges e = 4*it + w; lane l owns
// channels 4l..4l+3.
__global__ void __launch_bounds__(128)
k_main(const float* __restrict__ avec,
       const float* __restrict__ Wo,
       const float* __restrict__ Wg,
       const float* __restrict__ W2,
       float* __restrict__ out)
{
    __shared__ __align__(16) float4 s_meta[32];       // {src*32, tidx*32, frac, valid}
    __shared__ float s_logit[32][8];                  // final per-head logits
    __shared__ float s_alphaT[8][32];                 // [head][edge]
    __shared__ __align__(16) float s_vp[4][256];      // value partials per warp
    __shared__ __align__(16) float s_aggT[64][4];     // transposed aggregate
    __shared__ __align__(16) float4 s_ep[4][32];      // epilogue partials
    __shared__ __align__(16) float4 s_ygT[32];        // gated y, transposed
    __shared__ float s_y0[32];

    int n = blockIdx.x, t = threadIdx.x;
    int w = t >> 5, l = t & 31;

    if (t < KK) {
        int s = g_knn[n * KK + t];
        float d = g_dist[n * KK + t];
        float valid = (isfinite(d) && d > 1e-3f) ? 1.f : 0.f;
        float u = fminf(d * TB_SCALE, (float)(TB - 2) + 0.999f);
        u = fmaxf(u, 0.f);
        int i = (int)u;
        s_meta[t] = make_float4(__int_as_float(s << 5),     // src*32
                                __int_as_float(i << 5),     // tidx*32
                                u - (float)i, valid);
    }
    float4 ptgt4 = reinterpret_cast<const float4*>(g_Ptgt)[n * 32 + l];
    float4 av4   = reinterpret_cast<const float4*>(avec)[l];
    const uint2* psrcU = reinterpret_cast<const uint2*>(g_PsrcH);
    const uint2* posAU = reinterpret_cast<const uint2*>(g_posAH)
                         + (ptrdiff_t)(511 - n) * 32;
    const uint4* rbfU  = reinterpret_cast<const uint4*>(g_rbfTH);
    const float4* vno4 = reinterpret_cast<const float4*>(g_Vnode2);
    __syncthreads();

    // ---- logits: 4 edges in parallel (one per warp), 4 channels/lane ----
#pragma unroll 4
    for (int it = 0; it < 8; it++) {
        int e = 4 * it + w;
        if (e < KK) {
            float4 m = s_meta[e];
            int s32 = __float_as_int(m.x);
            int t32 = __float_as_int(m.y);
            uint2 psu = psrcU[s32 + l];
            uint2 pau = posAU[s32 + l];
            uint4 rv  = rbfU[t32 + l];
            float2 ps01 = __half22float2(*reinterpret_cast<__half2*>(&psu.x));
            float2 ps23 = __half22float2(*reinterpret_cast<__half2*>(&psu.y));
            float2 pa01 = __half22float2(*reinterpret_cast<__half2*>(&pau.x));
            float2 pa23 = __half22float2(*reinterpret_cast<__half2*>(&pau.y));
            float2 f0 = __half22float2(*reinterpret_cast<__half2*>(&rv.x));
            float2 f1 = __half22float2(*reinterpret_cast<__half2*>(&rv.y));
            float2 f2 = __half22float2(*reinterpret_cast<__half2*>(&rv.z));
            float2 f3 = __half22float2(*reinterpret_cast<__half2*>(&rv.w));
            float a0 = ptgt4.x + ps01.x + pa01.x + fmaf(m.z, f0.y, f0.x);
            float a1 = ptgt4.y + ps01.y + pa01.y + fmaf(m.z, f1.y, f1.x);
            float a2 = ptgt4.z + ps23.x + pa23.x + fmaf(m.z, f2.y, f2.x);
            float a3 = ptgt4.w + ps23.y + pa23.y + fmaf(m.z, f3.y, f3.x);
            float h0 = a0 * __fdividef(1.f, 1.f + __expf(-a0));   // silu
            float h1 = a1 * __fdividef(1.f, 1.f + __expf(-a1));
            float h2 = a2 * __fdividef(1.f, 1.f + __expf(-a2));
            float h3 = a3 * __fdividef(1.f, 1.f + __expf(-a3));
            float p = h0 * av4.x + h1 * av4.y + h2 * av4.z + h3 * av4.w;
            p += __shfl_xor_sync(0xffffffffu, p, 1);
            p += __shfl_xor_sync(0xffffffffu, p, 2);
            if ((l & 3) == 0)
                s_logit[e][l >> 2] = p;   // full 16-channel head sum
        }
    }
    __syncthreads();

    // ---- softmax (warp 0: 4 lanes per head) ----
    if (t < 32) {
        int h = t >> 2, q = t & 3;
        float lg[8], vv[8];
        float mx = -1e30f;
        int cnt = 0;
        for (int e = q; e < KK; e += 4, cnt++) {
            float s = s_logit[e][h];
            float valid = s_meta[e].w;
            float lgt = (s > 0.f) ? s : 0.2f * s;    // leaky_relu 0.2
            lgt = (valid > 0.f) ? lgt : -1e9f;
            lg[cnt] = lgt; vv[cnt] = valid;
            mx = fmaxf(mx, lgt);
        }
        mx = fmaxf(mx, __shfl_xor_sync(0xffffffffu, mx, 1));
        mx = fmaxf(mx, __shfl_xor_sync(0xffffffffu, mx, 2));
        float den = 0.f;
        cnt = 0;
        for (int e = q; e < KK; e += 4, cnt++) {
            float ex = __expf(lg[cnt] - mx) * vv[cnt];
            s_alphaT[h][e] = ex;
            den += ex;
        }
        den += __shfl_xor_sync(0xffffffffu, den, 1);
        den += __shfl_xor_sync(0xffffffffu, den, 2);
        float inv = __fdividef(1.f, den + 1e-9f);
        for (int e = q; e < KK; e += 4)
            s_alphaT[h][e] *= inv;
    }
    __syncthreads();

    // ---- value aggregation: 4 edges in parallel, 2x float4 / lane-iter ----
    {
        int h = ((4 * l) & 63) >> 3;                 // head for elems 4l..4l+3
        float4 accA = make_float4(0.f, 0.f, 0.f, 0.f);
        float4 accB = make_float4(0.f, 0.f, 0.f, 0.f);
#pragma unroll 4
        for (int it = 0; it < 8; it++) {
            int e = 4 * it + w;
            if (e < KK) {
                int s32 = __float_as_int(s_meta[e].x);
                float al = s_alphaT[h][e];
                int j = 2 * (s32 + l);               // = src*64 + 2l
                float4 vA = vno4[j];
                float4 vB = vno4[j + 1];
                accA.x = fmaf(al, vA.x, accA.x);
                accA.y = fmaf(al, vA.y, accA.y);
                accA.z = fmaf(al, vA.z, accA.z);
                accA.w = fmaf(al, vA.w, accA.w);
                accB.x = fmaf(al, vB.x, accB.x);
                accB.y = fmaf(al, vB.y, accB.y);
                accB.z = fmaf(al, vB.z, accB.z);
                accB.w = fmaf(al, vB.w, accB.w);
            }
        }
        float4* vp = reinterpret_cast<float4*>(&s_vp[w][8 * l]);
        vp[0] = accA;
        vp[1] = accB;
    }
    __syncthreads();
    {
        // combine 4 partials; value idx 2t -> aggT[t&63][t>>6], 2t+1 -> [.][+2]
        float2 p0 = reinterpret_cast<const float2*>(s_vp[0])[t];
        float2 p1 = reinterpret_cast<const float2*>(s_vp[1])[t];
        float2 p2 = reinterpret_cast<const float2*>(s_vp[2])[t];
        float2 p3 = reinterpret_cast<const float2*>(s_vp[3])[t];
        int cc = t & 63, r = t >> 6;
        s_aggT[cc][r]     = (p0.x + p1.x) + (p2.x + p3.x);
        s_aggT[cc][r + 2] = (p0.y + p1.y) + (p2.y + p3.y);
    }
    __syncthreads();

    // ---- epilogue: y = agg @ Wo (4 outputs/thread), gate, W2 ----
    int o = t & 31, s = t >> 5;
    const float4* aggT4 = reinterpret_cast<const float4*>(s_aggT);
    float4 acc4 = make_float4(0.f, 0.f, 0.f, 0.f);
#pragma unroll
    for (int i = 0; i < 16; i++) {
        int cc = s * 16 + i;
        float4 a4 = aggT4[cc];
        float wv = Wo[cc * 32 + o];
        acc4.x = fmaf(a4.x, wv, acc4.x);
        acc4.y = fmaf(a4.y, wv, acc4.y);
        acc4.z = fmaf(a4.z, wv, acc4.z);
        acc4.w = fmaf(a4.w, wv, acc4.w);
    }
    s_ep[s][o] = acc4;
    __syncthreads();
    float4 y4;
    if (t < 32) {
        float4 p0 = s_ep[0][t], p1 = s_ep[1][t], p2 = s_ep[2][t], p3 = s_ep[3][t];
        y4.x = p0.x + p1.x + p2.x + p3.x;
        y4.y = p0.y + p1.y + p2.y + p3.y;
        y4.z = p0.z + p1.z + p2.z + p3.z;
        y4.w = p0.w + p1.w + p2.w + p3.w;
        s_y0[t] = y4.x;
    }
    __syncthreads();
    if (t < 32) {
        float gg = 0.f;
#pragma unroll
        for (int j = 0; j < 32; j++) gg = fmaf(s_y0[j], Wg[j * 32 + t], gg);
        gg = gg * __fdividef(1.f, 1.f + __expf(-gg));  // silu gate
        y4.x *= gg; y4.y *= gg; y4.z *= gg; y4.w *= gg;
        s_ygT[t] = y4;
    }
    __syncthreads();
    float4 acc2 = make_float4(0.f, 0.f, 0.f, 0.f);
#pragma unroll
    for (int i = 0; i < 8; i++) {
        int j = s * 8 + i;
        float4 a4 = s_ygT[j];
        float wv = W2[j * 32 + o];
        acc2.x = fmaf(a4.x, wv, acc2.x);
        acc2.y = fmaf(a4.y, wv, acc2.y);
        acc2.z = fmaf(a4.z, wv, acc2.z);
        acc2.w = fmaf(a4.w, wv, acc2.w);
    }
    s_ep[s][o] = acc2;
    __syncthreads();
    if (t < 32) {
        float4 p0 = s_ep[0][t], p1 = s_ep[1][t], p2 = s_ep[2][t], p3 = s_ep[3][t];
        float* op = out + (size_t)n * 128;
        op[t]      = p0.x + p1.x + p2.x + p3.x;
        op[t + 32] = p0.y + p1.y + p2.y + p3.y;
        op[t + 64] = p0.z + p1.z + p2.z + p3.z;
        op[t + 96] = p0.w + p1.w + p2.w + p3.w;
    }
}

// ---------------- launch ----------------
extern "C" void kernel_launch(void* const* d_in, const int* in_sizes, int n_in,
                              void* d_out, int out_size)
{
    const float* rots     = (const float*)d_in[0];
    const float* trans    = (const float*)d_in[1];
    const float* node_emb = (const float*)d_in[2];
    const unsigned char* xm = (const unsigned char*)d_in[4];
    const unsigned char* nm = (const unsigned char*)d_in[5];
    const float* Wa = (const float*)d_in[6];
    const float* av = (const float*)d_in[7];
    const float* Wv = (const float*)d_in[8];
    const float* Wo = (const float*)d_in[9];
    const float* Wg = (const float*)d_in[10];
    const float* W2 = (const float*)d_in[11];
    float* out = (float*)d_out;

    k_prep<<<B_RBF, 128>>>(trans, rots, node_emb, xm, nm, Wa, Wv);
    k_main<<<NN, 128>>>(av, Wo, Wg, W2, out);
}